// round 9
// baseline (speedup 1.0000x reference)
#include <cuda_runtime.h>
#include <cuda_bf16.h>
#include <math.h>
#include <stdint.h>

#define T_   512
#define BB   64
#define HH   1024
#define N4   4096
#define RGRID 128   // blocks in persistent recurrence kernel

// ---------------- device scratch ----------------
__device__ float         g_zx[(size_t)T_ * BB * N4];        // x@Wi + b, fp32
__device__ __nv_bfloat16 g_xhi[(size_t)T_ * BB * HH];
__device__ __nv_bfloat16 g_xlo[(size_t)T_ * BB * HH];
__device__ __nv_bfloat16 g_WiT_hi[(size_t)N4 * HH];         // [n][k]
__device__ __nv_bfloat16 g_WiT_lo[(size_t)N4 * HH];
__device__ __nv_bfloat16 g_WhT_hi[(size_t)N4 * HH];         // [n][k] (pack source)
__device__ __nv_bfloat16 g_WhT_lo[(size_t)N4 * HH];

// Fragment-order operands for the recurrence MMA (no smem staging):
// A (h): [buf 2][m(4)][kc(64)][lane(32)] uint4
__device__ uint4 g_hfrag_hi[2][4 * 64 * 32];
__device__ uint4 g_hfrag_lo[2][4 * 64 * 32];
// B (Wh): [bid(128)][nhalf(2)][kc(64)][lane(32)] uint4
__device__ uint4 g_whfrag_hi[(size_t)128 * 2 * 64 * 32];
__device__ uint4 g_whfrag_lo[(size_t)128 * 2 * 64 * 32];

// ---------------- grid barrier ----------------
__device__ unsigned int          g_bar_count = 0;
__device__ volatile unsigned int g_bar_gen   = 0;

__device__ __forceinline__ void grid_barrier()
{
    __syncthreads();
    if (threadIdx.x == 0) {
        __threadfence();
        unsigned int gen = g_bar_gen;
        if (atomicAdd(&g_bar_count, 1) == RGRID - 1) {
            g_bar_count = 0;
            __threadfence();
            g_bar_gen = gen + 1;
        } else {
            while (g_bar_gen == gen) __nanosleep(32);
        }
        __threadfence();
    }
    __syncthreads();
}

// ---------------- helpers ----------------
__device__ __forceinline__ void bsplit(float v, __nv_bfloat16& hi, __nv_bfloat16& lo)
{
    hi = __float2bfloat16(v);
    lo = __float2bfloat16(v - __bfloat162float(hi));
}

__device__ __forceinline__ float fast_sigmoid(float x)
{
    return __frcp_rn(1.f + __expf(-x));
}
__device__ __forceinline__ float fast_tanh(float x)
{
    return 1.f - 2.f * __frcp_rn(__expf(2.f * x) + 1.f);
}

__device__ __forceinline__ void mma16816(float c[4],
                                         uint32_t a0, uint32_t a1, uint32_t a2, uint32_t a3,
                                         uint32_t b0, uint32_t b1)
{
    asm("mma.sync.aligned.m16n8k16.row.col.f32.bf16.bf16.f32 "
        "{%0,%1,%2,%3}, {%4,%5,%6,%7}, {%8,%9}, {%0,%1,%2,%3};"
        : "+f"(c[0]), "+f"(c[1]), "+f"(c[2]), "+f"(c[3])
        : "r"(a0), "r"(a1), "r"(a2), "r"(a3), "r"(b0), "r"(b1));
}

// ---------------------------------------------------------------------------
// Fused prep kernel (launch 1). Sections by blockIdx.x:
//  [0, 8192)        : split-convert x -> g_xhi/g_xlo  (4 float4 per thread)
//  [8192, 12288)    : transpose+split Wi -> g_WiT_hi/lo
//  [12288, 16384)   : transpose+split Wh -> g_WhT_hi/lo
//  [16384, 16512)   : h0 -> fragment buffer 0
// ---------------------------------------------------------------------------
__global__ __launch_bounds__(256) void prep_fused(const float* __restrict__ x,
                                                  const float* __restrict__ Wi,
                                                  const float* __restrict__ Wh,
                                                  const float* __restrict__ h0)
{
    const int blk = blockIdx.x;
    const int tid = threadIdx.x;

    if (blk < 8192) {
        const float4* xv = (const float4*)x;
        __nv_bfloat162* dh = reinterpret_cast<__nv_bfloat162*>(g_xhi);
        __nv_bfloat162* dl = reinterpret_cast<__nv_bfloat162*>(g_xlo);
#pragma unroll
        for (int j = 0; j < 4; j++) {
            int i = blk * 256 + tid + j * (8192 * 256);
            float4 v = xv[i];
            __nv_bfloat16 h0b,l0b,h1b,l1b,h2b,l2b,h3b,l3b;
            bsplit(v.x,h0b,l0b); bsplit(v.y,h1b,l1b);
            bsplit(v.z,h2b,l2b); bsplit(v.w,h3b,l3b);
            __nv_bfloat162 a; a.x=h0b; a.y=h1b; dh[2*i]   = a;
            __nv_bfloat162 b; b.x=h2b; b.y=h3b; dh[2*i+1] = b;
            __nv_bfloat162 c; c.x=l0b; c.y=l1b; dl[2*i]   = c;
            __nv_bfloat162 d; d.x=l2b; d.y=l3b; dl[2*i+1] = d;
        }
    } else if (blk < 16384) {
        __shared__ float tile[32][33];
        int which = (blk >= 12288);
        int tt = blk - (which ? 12288 : 8192);           // 0..4095
        const float* src = which ? Wh : Wi;
        int gx = (tt & 127) * 32;                        // n
        int gy = (tt >> 7) * 32;                         // k
#pragma unroll
        for (int i = 0; i < 4; i++) {
            int idx = tid + i * 256;
            int kl = idx >> 5, col = idx & 31;
            tile[kl][col] = src[(size_t)(gy + kl) * N4 + gx + col];
        }
        __syncthreads();
        __nv_bfloat16* dh = which ? g_WhT_hi : g_WiT_hi;
        __nv_bfloat16* dl = which ? g_WhT_lo : g_WiT_lo;
#pragma unroll
        for (int i = 0; i < 4; i++) {
            int idx = tid + i * 256;
            int nl = idx >> 5, kc = idx & 31;
            float v = tile[kc][nl];
            __nv_bfloat16 h, l; bsplit(v, h, l);
            dh[(size_t)(gx + nl) * HH + gy + kc] = h;
            dl[(size_t)(gx + nl) * HH + gy + kc] = l;
        }
    } else {
        int idx = (blk - 16384) * 256 + tid;             // 0 .. 64*512-1
        int b_ = idx >> 9;
        int p  = idx & 511;
        float v0 = h0[b_ * HH + 2 * p];
        float v1 = h0[b_ * HH + 2 * p + 1];
        __nv_bfloat16 h0b,l0b,h1b,l1b;
        bsplit(v0,h0b,l0b); bsplit(v1,h1b,l1b);
        __nv_bfloat162 wh; wh.x=h0b; wh.y=h1b;
        __nv_bfloat162 wl; wl.x=l0b; wl.y=l1b;

        int kc = p >> 3, within = p & 7;
        int tq = within & 3, whi = within >> 2;
        int m = b_ >> 4, r16 = b_ & 15;
        int gq = r16 & 7, top = r16 >> 3;
        int lane = gq * 4 + tq;
        int w = whi * 2 + top;
        uint32_t off = (uint32_t)(((m * 64 + kc) * 32 + lane) * 4 + w);
        ((uint32_t*)g_hfrag_hi[0])[off] = *(uint32_t*)&wh;
        ((uint32_t*)g_hfrag_lo[0])[off] = *(uint32_t*)&wl;
    }
}

// ---------------------------------------------------------------------------
// Launch 2 (fused): blocks [0,8192) = phase-1 GEMM tiles; [8192,10240) = Wh
// fragment pack (reads g_WhT written by launch 1).
// ---------------------------------------------------------------------------
__global__ __launch_bounds__(256) void gemm_wx_pack(const float* __restrict__ bias)
{
    const int blk = blockIdx.x;
    const int tid = threadIdx.x;

    if (blk >= 8192) {
        int widx = (blk - 8192) * 256 + tid;             // 0 .. 524287
        int lane  = widx & 31;
        int kc    = (widx >> 5) & 63;
        int nhalf = (widx >> 11) & 1;
        int bidn  = widx >> 12;
        int gq = lane >> 2, tq = lane & 3;

        const uint32_t* WH = (const uint32_t*)g_WhT_hi;  // [col][512 pairs]
        const uint32_t* WL = (const uint32_t*)g_WhT_lo;
        uint32_t hi[4], lo[4];
#pragma unroll
        for (int w = 0; w < 4; w++) {
            int j = w >> 1, b = w & 1;
            int zc = nhalf * 16 + j * 8 + gq;
            int col = (zc >> 3) * 1024 + bidn * 8 + (zc & 7);
            int pair = kc * 8 + tq + b * 4;
            hi[w] = WH[(size_t)col * 512 + pair];
            lo[w] = WL[(size_t)col * 512 + pair];
        }
        g_whfrag_hi[widx] = make_uint4(hi[0], hi[1], hi[2], hi[3]);
        g_whfrag_lo[widx] = make_uint4(lo[0], lo[1], lo[2], lo[3]);
        return;
    }

    // ---- phase-1 GEMM: 128x128 tile, 8 warps, warp 64x32, kt=32 ----
    __shared__ uint32_t sAh[128 * 20], sAl[128 * 20];
    __shared__ uint32_t sBh[128 * 20], sBl[128 * 20];

    const uint32_t* Xh = (const uint32_t*)g_xhi;
    const uint32_t* Xl = (const uint32_t*)g_xlo;
    const uint32_t* Wh = (const uint32_t*)g_WiT_hi;
    const uint32_t* Wl = (const uint32_t*)g_WiT_lo;

    const int bn   = (blk & 31) * 128;
    const int bm   = (blk >> 5) * 128;
    const int lane = tid & 31, wp = tid >> 5;
    const int g    = lane >> 2, tq = lane & 3;
    const int wm   = (wp >> 2) * 64;
    const int wn   = (wp & 3) * 32;
    const int r0   = wp * 2 + (lane >> 4);
    const int kw   = lane & 15;

    float acc[4][4][4] = {};
    uint32_t pAh[8], pAl[8], pBh[8], pBl[8];

    auto LOAD = [&](int kc) {
        int k0w = kc * 16;
#pragma unroll
        for (int i = 0; i < 8; i++) {
            int row = r0 + 16 * i;
            size_t ga = (size_t)(bm + row) * 512 + k0w + kw;
            size_t gb = (size_t)(bn + row) * 512 + k0w + kw;
            pAh[i] = Xh[ga]; pAl[i] = Xl[ga];
            pBh[i] = Wh[gb]; pBl[i] = Wl[gb];
        }
    };
    auto STORE = [&]() {
#pragma unroll
        for (int i = 0; i < 8; i++) {
            int row = r0 + 16 * i;
            sAh[row * 20 + kw] = pAh[i]; sAl[row * 20 + kw] = pAl[i];
            sBh[row * 20 + kw] = pBh[i]; sBl[row * 20 + kw] = pBl[i];
        }
    };

    LOAD(0); STORE(); __syncthreads();

    for (int kc = 0; kc < 32; kc++) {
        if (kc < 31) LOAD(kc + 1);
#pragma unroll
        for (int s = 0; s < 2; s++) {
            int kwb = s * 8;
            uint32_t bh[4][2], bl[4][2];
#pragma unroll
            for (int nf = 0; nf < 4; nf++) {
                int base = (wn + nf * 8 + g) * 20 + kwb + tq;
                bh[nf][0] = sBh[base]; bh[nf][1] = sBh[base + 4];
                bl[nf][0] = sBl[base]; bl[nf][1] = sBl[base + 4];
            }
#pragma unroll
            for (int mf = 0; mf < 4; mf++) {
                int rb = (wm + mf * 16 + g) * 20 + kwb + tq;
                uint32_t a0 = sAh[rb], a1 = sAh[rb + 160];
                uint32_t a2 = sAh[rb + 4], a3 = sAh[rb + 164];
                uint32_t l0 = sAl[rb], l1 = sAl[rb + 160];
                uint32_t l2 = sAl[rb + 4], l3 = sAl[rb + 164];
#pragma unroll
                for (int nf = 0; nf < 4; nf++) {
                    mma16816(acc[mf][nf], a0, a1, a2, a3, bh[nf][0], bh[nf][1]);
                    mma16816(acc[mf][nf], a0, a1, a2, a3, bl[nf][0], bl[nf][1]);
                    mma16816(acc[mf][nf], l0, l1, l2, l3, bh[nf][0], bh[nf][1]);
                }
            }
        }
        __syncthreads();
        if (kc < 31) { STORE(); __syncthreads(); }
    }

#pragma unroll
    for (int mf = 0; mf < 4; mf++) {
        int row0 = bm + wm + mf * 16 + g;
#pragma unroll
        for (int nf = 0; nf < 4; nf++) {
            int col = bn + wn + nf * 8 + tq * 2;
            float2 bb = *(const float2*)&bias[col];
            float2 v0, v1;
            v0.x = acc[mf][nf][0] + bb.x; v0.y = acc[mf][nf][1] + bb.y;
            v1.x = acc[mf][nf][2] + bb.x; v1.y = acc[mf][nf][3] + bb.y;
            *(float2*)&g_zx[(size_t)row0 * N4 + col]       = v0;
            *(float2*)&g_zx[(size_t)(row0 + 8) * N4 + col] = v1;
        }
    }
}

// ---------------------------------------------------------------------------
// Persistent recurrence (launch 3): 128 blocks x 256 thr.
// Warp decomposition: (ks in 4 K-quarters) x (mp in 2 m-halves).
// Each warp: m32 x n32 over K/4 (16 k16 chunks). A read exactly once per
// block; B read twice. One-stage smem reduction (4 partials -> 1) per mp.
// ---------------------------------------------------------------------------
__global__ __launch_bounds__(256, 1)
void lstm_rec_mma(const float* __restrict__ c0,
                  float* __restrict__ ys,
                  float* __restrict__ cT,
                  float* __restrict__ hT)
{
    __shared__ float Zpart[6][1024];   // 24 KB: partials from ks=1..3, both mp
    __shared__ float Z[64][33];        // final z tile for pointwise gather

    const int tid  = threadIdx.x, bid = blockIdx.x;
    const int lane = tid & 31, wp = tid >> 5;
    const int gq   = lane >> 2, tq = lane & 3;
    const int ks   = wp & 3;           // K quarter: chunks [ks*16, ks*16+16)
    const int mp   = wp >> 2;          // m half: frags {2mp, 2mp+1} (rows mp*32..+31)
    const int jb   = bid * 8;

    const uint4* WBh0 = g_whfrag_hi + ((size_t)(bid * 2 + 0) * 64) * 32;
    const uint4* WBl0 = g_whfrag_lo + ((size_t)(bid * 2 + 0) * 64) * 32;
    const uint4* WBh1 = g_whfrag_hi + ((size_t)(bid * 2 + 1) * 64) * 32;
    const uint4* WBl1 = g_whfrag_lo + ((size_t)(bid * 2 + 1) * 64) * 32;

    // pointwise decode
    const int pb  = tid >> 2;
    const int jj  = (tid & 3) * 2;
    const int j0  = jb + jj;
    const int p_g   = j0 >> 1;
    const int kcw   = p_g >> 3, within = p_g & 7;
    const int ptq   = within & 3, pwhi = within >> 2;
    const int pm    = pb >> 4, r16 = pb & 15;
    const int pg    = r16 & 7, ptop = r16 >> 3;
    const uint32_t hoff = (uint32_t)((((pm * 64 + kcw) * 32) + pg * 4 + ptq) * 4
                                     + pwhi * 2 + ptop);

    for (int t = 0; t < T_; t++) {
        const uint4* AH = g_hfrag_hi[t & 1];
        const uint4* AL = g_hfrag_lo[t & 1];

        // ---- prefetch pointwise operands ----
        const float* zx = g_zx + (size_t)t * BB * N4 + (size_t)pb * N4;
        const float* cp = (t == 0) ? c0 : cT;
        float2 xi = *(const float2*)&zx[j0];
        float2 xf = *(const float2*)&zx[HH + j0];
        float2 xg = *(const float2*)&zx[2 * HH + j0];
        float2 xo = *(const float2*)&zx[3 * HH + j0];
        float2 cv = *(const float2*)&cp[(size_t)pb * HH + j0];

        // acc[mm][nf][r]: mm = m-frag within pair, nf = nhalf*2+j
        float acc[2][4][4];
#pragma unroll
        for (int a = 0; a < 2; a++)
#pragma unroll
            for (int b = 0; b < 4; b++)
#pragma unroll
                for (int r = 0; r < 4; r++) acc[a][b][r] = 0.f;

        uint4 aH[2][2], aL[2][2], bH[2][2], bL[2][2];   // [buf][mm / nhalf]
        const int kb = ks * 16;

        {   // prologue: chunk kb
            int off = kb * 32 + lane;
#pragma unroll
            for (int mm = 0; mm < 2; mm++) {
                aH[0][mm] = AH[(2 * mp + mm) * 2048 + off];
                aL[0][mm] = AL[(2 * mp + mm) * 2048 + off];
            }
            bH[0][0] = WBh0[off]; bH[0][1] = WBh1[off];
            bL[0][0] = WBl0[off]; bL[0][1] = WBl1[off];
        }

#pragma unroll 4
        for (int i = 0; i < 16; i++) {
            int cur = i & 1, nxt = cur ^ 1;
            if (i < 15) {
                int off = (kb + i + 1) * 32 + lane;
#pragma unroll
                for (int mm = 0; mm < 2; mm++) {
                    aH[nxt][mm] = AH[(2 * mp + mm) * 2048 + off];
                    aL[nxt][mm] = AL[(2 * mp + mm) * 2048 + off];
                }
                bH[nxt][0] = WBh0[off]; bH[nxt][1] = WBh1[off];
                bL[nxt][0] = WBl0[off]; bL[nxt][1] = WBl1[off];
            }
#pragma unroll
            for (int mm = 0; mm < 2; mm++) {
                uint4 ah = aH[cur][mm], al = aL[cur][mm];
#pragma unroll
                for (int nh = 0; nh < 2; nh++) {
                    uint4 bh = bH[cur][nh], bl = bL[cur][nh];
                    mma16816(acc[mm][nh*2+0], ah.x, ah.y, ah.z, ah.w, bh.x, bh.y);
                    mma16816(acc[mm][nh*2+0], ah.x, ah.y, ah.z, ah.w, bl.x, bl.y);
                    mma16816(acc[mm][nh*2+0], al.x, al.y, al.z, al.w, bh.x, bh.y);
                    mma16816(acc[mm][nh*2+1], ah.x, ah.y, ah.z, ah.w, bh.z, bh.w);
                    mma16816(acc[mm][nh*2+1], ah.x, ah.y, ah.z, ah.w, bl.z, bl.w);
                    mma16816(acc[mm][nh*2+1], al.x, al.y, al.z, al.w, bh.z, bh.w);
                }
            }
        }

        // ---- one-stage K-split reduction: ks=1..3 -> smem, ks=0 sums ----
        if (ks != 0) {
            float* zp = Zpart[mp * 3 + ks - 1];
#pragma unroll
            for (int mm = 0; mm < 2; mm++)
#pragma unroll
                for (int nf = 0; nf < 4; nf++)
#pragma unroll
                    for (int r = 0; r < 4; r++)
                        zp[((mm * 4 + nf) * 4 + r) * 32 + lane] = acc[mm][nf][r];
        }
        __syncthreads();
        if (ks == 0) {
#pragma unroll
            for (int s = 0; s < 3; s++) {
                const float* zp = Zpart[mp * 3 + s];
#pragma unroll
                for (int mm = 0; mm < 2; mm++)
#pragma unroll
                    for (int nf = 0; nf < 4; nf++)
#pragma unroll
                        for (int r = 0; r < 4; r++)
                            acc[mm][nf][r] += zp[((mm * 4 + nf) * 4 + r) * 32 + lane];
            }
            // write final Z tile (rows mp*32 .. mp*32+31)
#pragma unroll
            for (int mm = 0; mm < 2; mm++) {
                int row = mp * 32 + mm * 16 + gq;
#pragma unroll
                for (int nf = 0; nf < 4; nf++) {
                    int zb = (nf >> 1) * 16 + (nf & 1) * 8 + tq * 2;
                    Z[row][zb]         = acc[mm][nf][0];
                    Z[row][zb + 1]     = acc[mm][nf][1];
                    Z[row + 8][zb]     = acc[mm][nf][2];
                    Z[row + 8][zb + 1] = acc[mm][nf][3];
                }
            }
        }
        __syncthreads();

        // ---- pointwise gates ----
        {
            float* ys_t = ys + (size_t)t * BB * HH;
            uint32_t* nhh = (uint32_t*)g_hfrag_hi[(t + 1) & 1];
            uint32_t* nhl = (uint32_t*)g_hfrag_lo[(t + 1) & 1];

            float h2[2], c2[2];
#pragma unroll
            for (int e = 0; e < 2; e++) {
                int zc = jj + e;
                float zi = Z[pb][zc]      + (e ? xi.y : xi.x);
                float zf = Z[pb][8 + zc]  + (e ? xf.y : xf.x);
                float zg = Z[pb][16 + zc] + (e ? xg.y : xg.x);
                float zo = Z[pb][24 + zc] + (e ? xo.y : xo.x);

                float ig = fast_sigmoid(zi);
                float fg = fast_sigmoid(zf);
                float gg = fast_tanh(zg);
                float og = fast_sigmoid(zo);

                float cc = fg * (e ? cv.y : cv.x) + ig * gg;
                c2[e] = cc;
                h2[e] = og * fast_tanh(cc);
            }

            *(float2*)&cT[(size_t)pb * HH + j0]   = *(float2*)c2;
            *(float2*)&ys_t[(size_t)pb * HH + j0] = *(float2*)h2;
            if (t == T_ - 1) *(float2*)&hT[(size_t)pb * HH + j0] = *(float2*)h2;

            __nv_bfloat16 h0b,l0b,h1b,l1b;
            bsplit(h2[0], h0b, l0b); bsplit(h2[1], h1b, l1b);
            __nv_bfloat162 wh; wh.x = h0b; wh.y = h1b;
            __nv_bfloat162 wl; wl.x = l0b; wl.y = l1b;
            nhh[hoff] = *(uint32_t*)&wh;
            nhl[hoff] = *(uint32_t*)&wl;
        }

        grid_barrier();
    }
}

// ---------------------------------------------------------------------------
extern "C" void kernel_launch(void* const* d_in, const int* in_sizes, int n_in,
                              void* d_out, int out_size)
{
    const float* x  = (const float*)d_in[0];   // [T,B,D]
    const float* c0 = (const float*)d_in[1];   // [B,H]
    const float* h0 = (const float*)d_in[2];   // [B,H]
    const float* Wi = (const float*)d_in[3];   // [D,4H]
    const float* Wh = (const float*)d_in[4];   // [H,4H]
    const float* b  = (const float*)d_in[5];   // [4H]

    float* out = (float*)d_out;
    float* ys = out;                                  // [T,B,H]
    float* cT = out + (size_t)T_ * BB * HH;           // [B,H]
    float* hT = cT + (size_t)BB * HH;                 // [B,H]

    prep_fused<<<16512, 256>>>(x, Wi, Wh, h0);        // launch 1
    gemm_wx_pack<<<10240, 256>>>(b);                  // launch 2
    lstm_rec_mma<<<RGRID, 256>>>(c0, ys, cT, hT);     // launch 3
}

// round 10
// speedup vs baseline: 1.5414x; 1.5414x over previous
#include <cuda_runtime.h>
#include <cuda_bf16.h>
#include <math.h>
#include <stdint.h>

#define T_   512
#define BB   64
#define HH   1024
#define N4   4096
#define RGRID 128   // blocks in persistent recurrence kernel

// ---------------- device scratch ----------------
__device__ float         g_zx[(size_t)T_ * BB * N4];        // x@Wi + b, fp32
__device__ __nv_bfloat16 g_xhi[(size_t)T_ * BB * HH];
__device__ __nv_bfloat16 g_xlo[(size_t)T_ * BB * HH];
__device__ __nv_bfloat16 g_WiT_hi[(size_t)N4 * HH];         // [n][k]
__device__ __nv_bfloat16 g_WiT_lo[(size_t)N4 * HH];
__device__ __nv_bfloat16 g_WhT_hi[(size_t)N4 * HH];         // [n][k] (pack source)
__device__ __nv_bfloat16 g_WhT_lo[(size_t)N4 * HH];

// Fragment-order operands for the recurrence MMA (no smem staging):
// A (h): [buf 2][m(4)][kc(64)][lane(32)] uint4
__device__ uint4 g_hfrag_hi[2][4 * 64 * 32];
__device__ uint4 g_hfrag_lo[2][4 * 64 * 32];
// B (Wh): [bid(128)][nhalf(2)][kc(64)][lane(32)] uint4
__device__ uint4 g_whfrag_hi[(size_t)128 * 2 * 64 * 32];
__device__ uint4 g_whfrag_lo[(size_t)128 * 2 * 64 * 32];

// ---------------- grid barrier ----------------
__device__ unsigned int          g_bar_count = 0;
__device__ volatile unsigned int g_bar_gen   = 0;

__device__ __forceinline__ void grid_barrier()
{
    __syncthreads();
    if (threadIdx.x == 0) {
        __threadfence();
        unsigned int gen = g_bar_gen;
        if (atomicAdd(&g_bar_count, 1) == RGRID - 1) {
            g_bar_count = 0;
            __threadfence();
            g_bar_gen = gen + 1;
        } else {
            while (g_bar_gen == gen) __nanosleep(32);
        }
        __threadfence();
    }
    __syncthreads();
}

// ---------------- helpers ----------------
__device__ __forceinline__ void bsplit(float v, __nv_bfloat16& hi, __nv_bfloat16& lo)
{
    hi = __float2bfloat16(v);
    lo = __float2bfloat16(v - __bfloat162float(hi));
}

__device__ __forceinline__ float fast_sigmoid(float x)
{
    return __frcp_rn(1.f + __expf(-x));
}
__device__ __forceinline__ float fast_tanh(float x)
{
    return 1.f - 2.f * __frcp_rn(__expf(2.f * x) + 1.f);
}

__device__ __forceinline__ void mma16816(float c[4],
                                         uint32_t a0, uint32_t a1, uint32_t a2, uint32_t a3,
                                         uint32_t b0, uint32_t b1)
{
    asm("mma.sync.aligned.m16n8k16.row.col.f32.bf16.bf16.f32 "
        "{%0,%1,%2,%3}, {%4,%5,%6,%7}, {%8,%9}, {%0,%1,%2,%3};"
        : "+f"(c[0]), "+f"(c[1]), "+f"(c[2]), "+f"(c[3])
        : "r"(a0), "r"(a1), "r"(a2), "r"(a3), "r"(b0), "r"(b1));
}

// ---------------------------------------------------------------------------
// Fused prep kernel (launch 1). Sections by blockIdx.x:
//  [0, 8192)        : split-convert x -> g_xhi/g_xlo  (4 float4 per thread)
//  [8192, 12288)    : transpose+split Wi -> g_WiT_hi/lo
//  [12288, 16384)   : transpose+split Wh -> g_WhT_hi/lo
//  [16384, 16512)   : h0 -> fragment buffer 0
// ---------------------------------------------------------------------------
__global__ __launch_bounds__(256) void prep_fused(const float* __restrict__ x,
                                                  const float* __restrict__ Wi,
                                                  const float* __restrict__ Wh,
                                                  const float* __restrict__ h0)
{
    const int blk = blockIdx.x;
    const int tid = threadIdx.x;

    if (blk < 8192) {
        const float4* xv = (const float4*)x;
        __nv_bfloat162* dh = reinterpret_cast<__nv_bfloat162*>(g_xhi);
        __nv_bfloat162* dl = reinterpret_cast<__nv_bfloat162*>(g_xlo);
#pragma unroll
        for (int j = 0; j < 4; j++) {
            int i = blk * 256 + tid + j * (8192 * 256);
            float4 v = xv[i];
            __nv_bfloat16 h0b,l0b,h1b,l1b,h2b,l2b,h3b,l3b;
            bsplit(v.x,h0b,l0b); bsplit(v.y,h1b,l1b);
            bsplit(v.z,h2b,l2b); bsplit(v.w,h3b,l3b);
            __nv_bfloat162 a; a.x=h0b; a.y=h1b; dh[2*i]   = a;
            __nv_bfloat162 b; b.x=h2b; b.y=h3b; dh[2*i+1] = b;
            __nv_bfloat162 c; c.x=l0b; c.y=l1b; dl[2*i]   = c;
            __nv_bfloat162 d; d.x=l2b; d.y=l3b; dl[2*i+1] = d;
        }
    } else if (blk < 16384) {
        __shared__ float tile[32][33];
        int which = (blk >= 12288);
        int tt = blk - (which ? 12288 : 8192);           // 0..4095
        const float* src = which ? Wh : Wi;
        int gx = (tt & 127) * 32;                        // n
        int gy = (tt >> 7) * 32;                         // k
#pragma unroll
        for (int i = 0; i < 4; i++) {
            int idx = tid + i * 256;
            int kl = idx >> 5, col = idx & 31;
            tile[kl][col] = src[(size_t)(gy + kl) * N4 + gx + col];
        }
        __syncthreads();
        __nv_bfloat16* dh = which ? g_WhT_hi : g_WiT_hi;
        __nv_bfloat16* dl = which ? g_WhT_lo : g_WiT_lo;
#pragma unroll
        for (int i = 0; i < 4; i++) {
            int idx = tid + i * 256;
            int nl = idx >> 5, kc = idx & 31;
            float v = tile[kc][nl];
            __nv_bfloat16 h, l; bsplit(v, h, l);
            dh[(size_t)(gx + nl) * HH + gy + kc] = h;
            dl[(size_t)(gx + nl) * HH + gy + kc] = l;
        }
    } else {
        int idx = (blk - 16384) * 256 + tid;             // 0 .. 64*512-1
        int b_ = idx >> 9;
        int p  = idx & 511;
        float v0 = h0[b_ * HH + 2 * p];
        float v1 = h0[b_ * HH + 2 * p + 1];
        __nv_bfloat16 h0b,l0b,h1b,l1b;
        bsplit(v0,h0b,l0b); bsplit(v1,h1b,l1b);
        __nv_bfloat162 wh; wh.x=h0b; wh.y=h1b;
        __nv_bfloat162 wl; wl.x=l0b; wl.y=l1b;

        int kc = p >> 3, within = p & 7;
        int tq = within & 3, whi = within >> 2;
        int m = b_ >> 4, r16 = b_ & 15;
        int gq = r16 & 7, top = r16 >> 3;
        int lane = gq * 4 + tq;
        int w = whi * 2 + top;
        uint32_t off = (uint32_t)(((m * 64 + kc) * 32 + lane) * 4 + w);
        ((uint32_t*)g_hfrag_hi[0])[off] = *(uint32_t*)&wh;
        ((uint32_t*)g_hfrag_lo[0])[off] = *(uint32_t*)&wl;
    }
}

// ---------------------------------------------------------------------------
// Launch 2 (fused): blocks [0,8192) = phase-1 GEMM tiles; [8192,10240) = Wh
// fragment pack (reads g_WhT written by launch 1).
// ---------------------------------------------------------------------------
__global__ __launch_bounds__(256) void gemm_wx_pack(const float* __restrict__ bias)
{
    const int blk = blockIdx.x;
    const int tid = threadIdx.x;

    if (blk >= 8192) {
        int widx = (blk - 8192) * 256 + tid;             // 0 .. 524287
        int lane  = widx & 31;
        int kc    = (widx >> 5) & 63;
        int nhalf = (widx >> 11) & 1;
        int bidn  = widx >> 12;
        int gq = lane >> 2, tq = lane & 3;

        const uint32_t* WH = (const uint32_t*)g_WhT_hi;  // [col][512 pairs]
        const uint32_t* WL = (const uint32_t*)g_WhT_lo;
        uint32_t hi[4], lo[4];
#pragma unroll
        for (int w = 0; w < 4; w++) {
            int j = w >> 1, b = w & 1;
            int zc = nhalf * 16 + j * 8 + gq;
            int col = (zc >> 3) * 1024 + bidn * 8 + (zc & 7);
            int pair = kc * 8 + tq + b * 4;
            hi[w] = WH[(size_t)col * 512 + pair];
            lo[w] = WL[(size_t)col * 512 + pair];
        }
        g_whfrag_hi[widx] = make_uint4(hi[0], hi[1], hi[2], hi[3]);
        g_whfrag_lo[widx] = make_uint4(lo[0], lo[1], lo[2], lo[3]);
        return;
    }

    // ---- phase-1 GEMM: 128x128 tile, 8 warps, warp 64x32, kt=32 ----
    __shared__ uint32_t sAh[128 * 20], sAl[128 * 20];
    __shared__ uint32_t sBh[128 * 20], sBl[128 * 20];

    const uint32_t* Xh = (const uint32_t*)g_xhi;
    const uint32_t* Xl = (const uint32_t*)g_xlo;
    const uint32_t* Wh = (const uint32_t*)g_WiT_hi;
    const uint32_t* Wl = (const uint32_t*)g_WiT_lo;

    const int bn   = (blk & 31) * 128;
    const int bm   = (blk >> 5) * 128;
    const int lane = tid & 31, wp = tid >> 5;
    const int g    = lane >> 2, tq = lane & 3;
    const int wm   = (wp >> 2) * 64;
    const int wn   = (wp & 3) * 32;
    const int r0   = wp * 2 + (lane >> 4);
    const int kw   = lane & 15;

    float acc[4][4][4] = {};
    uint32_t pAh[8], pAl[8], pBh[8], pBl[8];

    auto LOAD = [&](int kc) {
        int k0w = kc * 16;
#pragma unroll
        for (int i = 0; i < 8; i++) {
            int row = r0 + 16 * i;
            size_t ga = (size_t)(bm + row) * 512 + k0w + kw;
            size_t gb = (size_t)(bn + row) * 512 + k0w + kw;
            pAh[i] = Xh[ga]; pAl[i] = Xl[ga];
            pBh[i] = Wh[gb]; pBl[i] = Wl[gb];
        }
    };
    auto STORE = [&]() {
#pragma unroll
        for (int i = 0; i < 8; i++) {
            int row = r0 + 16 * i;
            sAh[row * 20 + kw] = pAh[i]; sAl[row * 20 + kw] = pAl[i];
            sBh[row * 20 + kw] = pBh[i]; sBl[row * 20 + kw] = pBl[i];
        }
    };

    LOAD(0); STORE(); __syncthreads();

    for (int kc = 0; kc < 32; kc++) {
        if (kc < 31) LOAD(kc + 1);
#pragma unroll
        for (int s = 0; s < 2; s++) {
            int kwb = s * 8;
            uint32_t bh[4][2], bl[4][2];
#pragma unroll
            for (int nf = 0; nf < 4; nf++) {
                int base = (wn + nf * 8 + g) * 20 + kwb + tq;
                bh[nf][0] = sBh[base]; bh[nf][1] = sBh[base + 4];
                bl[nf][0] = sBl[base]; bl[nf][1] = sBl[base + 4];
            }
#pragma unroll
            for (int mf = 0; mf < 4; mf++) {
                int rb = (wm + mf * 16 + g) * 20 + kwb + tq;
                uint32_t a0 = sAh[rb], a1 = sAh[rb + 160];
                uint32_t a2 = sAh[rb + 4], a3 = sAh[rb + 164];
                uint32_t l0 = sAl[rb], l1 = sAl[rb + 160];
                uint32_t l2 = sAl[rb + 4], l3 = sAl[rb + 164];
#pragma unroll
                for (int nf = 0; nf < 4; nf++) {
                    mma16816(acc[mf][nf], a0, a1, a2, a3, bh[nf][0], bh[nf][1]);
                    mma16816(acc[mf][nf], a0, a1, a2, a3, bl[nf][0], bl[nf][1]);
                    mma16816(acc[mf][nf], l0, l1, l2, l3, bh[nf][0], bh[nf][1]);
                }
            }
        }
        __syncthreads();
        if (kc < 31) { STORE(); __syncthreads(); }
    }

#pragma unroll
    for (int mf = 0; mf < 4; mf++) {
        int row0 = bm + wm + mf * 16 + g;
#pragma unroll
        for (int nf = 0; nf < 4; nf++) {
            int col = bn + wn + nf * 8 + tq * 2;
            float2 bb = *(const float2*)&bias[col];
            float2 v0, v1;
            v0.x = acc[mf][nf][0] + bb.x; v0.y = acc[mf][nf][1] + bb.y;
            v1.x = acc[mf][nf][2] + bb.x; v1.y = acc[mf][nf][3] + bb.y;
            *(float2*)&g_zx[(size_t)row0 * N4 + col]       = v0;
            *(float2*)&g_zx[(size_t)(row0 + 8) * N4 + col] = v1;
        }
    }
}

// ---------------------------------------------------------------------------
// Persistent recurrence (launch 3): 128 blocks x 256 thr.
// Warp decomposition: (ks in 4 K-quarters) x (mp in 2 m-halves); each warp
// m32 x n32 over 16 k16 chunks. 4-slot register pipeline (3 chunks of
// prefetch slack) to cover loaded-L2 latency. One-stage smem reduction.
// ---------------------------------------------------------------------------
__global__ __launch_bounds__(256, 1)
void lstm_rec_mma(const float* __restrict__ c0,
                  float* __restrict__ ys,
                  float* __restrict__ cT,
                  float* __restrict__ hT)
{
    __shared__ float Zpart[6][1024];   // 24 KB: partials from ks=1..3, both mp
    __shared__ float Z[64][33];        // final z tile for pointwise gather

    const int tid  = threadIdx.x, bid = blockIdx.x;
    const int lane = tid & 31, wp = tid >> 5;
    const int gq   = lane >> 2, tq = lane & 3;
    const int ks   = wp & 3;           // K quarter: chunks [ks*16, ks*16+16)
    const int mp   = wp >> 2;          // m half: frags {2mp, 2mp+1}
    const int jb   = bid * 8;

    const uint4* WBh0 = g_whfrag_hi + ((size_t)(bid * 2 + 0) * 64) * 32;
    const uint4* WBl0 = g_whfrag_lo + ((size_t)(bid * 2 + 0) * 64) * 32;
    const uint4* WBh1 = g_whfrag_hi + ((size_t)(bid * 2 + 1) * 64) * 32;
    const uint4* WBl1 = g_whfrag_lo + ((size_t)(bid * 2 + 1) * 64) * 32;

    // pointwise decode
    const int pb  = tid >> 2;
    const int jj  = (tid & 3) * 2;
    const int j0  = jb + jj;
    const int p_g   = j0 >> 1;
    const int kcw   = p_g >> 3, within = p_g & 7;
    const int ptq   = within & 3, pwhi = within >> 2;
    const int pm    = pb >> 4, r16 = pb & 15;
    const int pg    = r16 & 7, ptop = r16 >> 3;
    const uint32_t hoff = (uint32_t)((((pm * 64 + kcw) * 32) + pg * 4 + ptq) * 4
                                     + pwhi * 2 + ptop);

    for (int t = 0; t < T_; t++) {
        const uint4* AH = g_hfrag_hi[t & 1];
        const uint4* AL = g_hfrag_lo[t & 1];

        // ---- prefetch pointwise operands ----
        const float* zx = g_zx + (size_t)t * BB * N4 + (size_t)pb * N4;
        const float* cp = (t == 0) ? c0 : cT;
        float2 xi = *(const float2*)&zx[j0];
        float2 xf = *(const float2*)&zx[HH + j0];
        float2 xg = *(const float2*)&zx[2 * HH + j0];
        float2 xo = *(const float2*)&zx[3 * HH + j0];
        float2 cv = *(const float2*)&cp[(size_t)pb * HH + j0];

        float acc[2][4][4];
#pragma unroll
        for (int a = 0; a < 2; a++)
#pragma unroll
            for (int b = 0; b < 4; b++)
#pragma unroll
                for (int r = 0; r < 4; r++) acc[a][b][r] = 0.f;

        // 4-slot pipeline: slot s holds chunk (i) with i % 4 == s
        uint4 aH[4][2], aL[4][2], bH[4][2], bL[4][2];
        const int kb = ks * 16;

        auto LOADC = [&](int i, int slot) {
            int off = (kb + i) * 32 + lane;
#pragma unroll
            for (int mm = 0; mm < 2; mm++) {
                aH[slot][mm] = AH[(2 * mp + mm) * 2048 + off];
                aL[slot][mm] = AL[(2 * mp + mm) * 2048 + off];
            }
            bH[slot][0] = WBh0[off]; bH[slot][1] = WBh1[off];
            bL[slot][0] = WBl0[off]; bL[slot][1] = WBl1[off];
        };

        LOADC(0, 0); LOADC(1, 1); LOADC(2, 2);

#pragma unroll 4
        for (int i = 0; i < 16; i++) {
            int cur = i & 3;
            if (i + 3 < 16) LOADC(i + 3, (i + 3) & 3);
#pragma unroll
            for (int mm = 0; mm < 2; mm++) {
                uint4 ah = aH[cur][mm], al = aL[cur][mm];
#pragma unroll
                for (int nh = 0; nh < 2; nh++) {
                    uint4 bh = bH[cur][nh], bl = bL[cur][nh];
                    mma16816(acc[mm][nh*2+0], ah.x, ah.y, ah.z, ah.w, bh.x, bh.y);
                    mma16816(acc[mm][nh*2+0], ah.x, ah.y, ah.z, ah.w, bl.x, bl.y);
                    mma16816(acc[mm][nh*2+0], al.x, al.y, al.z, al.w, bh.x, bh.y);
                    mma16816(acc[mm][nh*2+1], ah.x, ah.y, ah.z, ah.w, bh.z, bh.w);
                    mma16816(acc[mm][nh*2+1], ah.x, ah.y, ah.z, ah.w, bl.z, bl.w);
                    mma16816(acc[mm][nh*2+1], al.x, al.y, al.z, al.w, bh.z, bh.w);
                }
            }
        }

        // ---- one-stage K-split reduction: ks=1..3 -> smem, ks=0 sums ----
        if (ks != 0) {
            float* zp = Zpart[mp * 3 + ks - 1];
#pragma unroll
            for (int mm = 0; mm < 2; mm++)
#pragma unroll
                for (int nf = 0; nf < 4; nf++)
#pragma unroll
                    for (int r = 0; r < 4; r++)
                        zp[((mm * 4 + nf) * 4 + r) * 32 + lane] = acc[mm][nf][r];
        }
        __syncthreads();
        if (ks == 0) {
#pragma unroll
            for (int s = 0; s < 3; s++) {
                const float* zp = Zpart[mp * 3 + s];
#pragma unroll
                for (int mm = 0; mm < 2; mm++)
#pragma unroll
                    for (int nf = 0; nf < 4; nf++)
#pragma unroll
                        for (int r = 0; r < 4; r++)
                            acc[mm][nf][r] += zp[((mm * 4 + nf) * 4 + r) * 32 + lane];
            }
#pragma unroll
            for (int mm = 0; mm < 2; mm++) {
                int row = mp * 32 + mm * 16 + gq;
#pragma unroll
                for (int nf = 0; nf < 4; nf++) {
                    int zb = (nf >> 1) * 16 + (nf & 1) * 8 + tq * 2;
                    Z[row][zb]         = acc[mm][nf][0];
                    Z[row][zb + 1]     = acc[mm][nf][1];
                    Z[row + 8][zb]     = acc[mm][nf][2];
                    Z[row + 8][zb + 1] = acc[mm][nf][3];
                }
            }
        }
        __syncthreads();

        // ---- pointwise gates ----
        {
            float* ys_t = ys + (size_t)t * BB * HH;
            uint32_t* nhh = (uint32_t*)g_hfrag_hi[(t + 1) & 1];
            uint32_t* nhl = (uint32_t*)g_hfrag_lo[(t + 1) & 1];

            float h2[2], c2[2];
#pragma unroll
            for (int e = 0; e < 2; e++) {
                int zc = jj + e;
                float zi = Z[pb][zc]      + (e ? xi.y : xi.x);
                float zf = Z[pb][8 + zc]  + (e ? xf.y : xf.x);
                float zg = Z[pb][16 + zc] + (e ? xg.y : xg.x);
                float zo = Z[pb][24 + zc] + (e ? xo.y : xo.x);

                float ig = fast_sigmoid(zi);
                float fg = fast_sigmoid(zf);
                float gg = fast_tanh(zg);
                float og = fast_sigmoid(zo);

                float cc = fg * (e ? cv.y : cv.x) + ig * gg;
                c2[e] = cc;
                h2[e] = og * fast_tanh(cc);
            }

            *(float2*)&cT[(size_t)pb * HH + j0]   = *(float2*)c2;
            *(float2*)&ys_t[(size_t)pb * HH + j0] = *(float2*)h2;
            if (t == T_ - 1) *(float2*)&hT[(size_t)pb * HH + j0] = *(float2*)h2;

            __nv_bfloat16 h0b,l0b,h1b,l1b;
            bsplit(h2[0], h0b, l0b); bsplit(h2[1], h1b, l1b);
            __nv_bfloat162 wh; wh.x = h0b; wh.y = h1b;
            __nv_bfloat162 wl; wl.x = l0b; wl.y = l1b;
            nhh[hoff] = *(uint32_t*)&wh;
            nhl[hoff] = *(uint32_t*)&wl;
        }

        grid_barrier();
    }
}

// ---------------------------------------------------------------------------
extern "C" void kernel_launch(void* const* d_in, const int* in_sizes, int n_in,
                              void* d_out, int out_size)
{
    const float* x  = (const float*)d_in[0];   // [T,B,D]
    const float* c0 = (const float*)d_in[1];   // [B,H]
    const float* h0 = (const float*)d_in[2];   // [B,H]
    const float* Wi = (const float*)d_in[3];   // [D,4H]
    const float* Wh = (const float*)d_in[4];   // [H,4H]
    const float* b  = (const float*)d_in[5];   // [4H]

    float* out = (float*)d_out;
    float* ys = out;                                  // [T,B,H]
    float* cT = out + (size_t)T_ * BB * HH;           // [B,H]
    float* hT = cT + (size_t)BB * HH;                 // [B,H]

    prep_fused<<<16512, 256>>>(x, Wi, Wh, h0);        // launch 1
    gemm_wx_pack<<<10240, 256>>>(b);                  // launch 2
    lstm_rec_mma<<<RGRID, 256>>>(c0, ys, cT, hT);     // launch 3
}

// round 11
// speedup vs baseline: 1.5418x; 1.0002x over previous
#include <cuda_runtime.h>
#include <cuda_bf16.h>
#include <math.h>
#include <stdint.h>

#define T_   512
#define BB   64
#define HH   1024
#define N4   4096
#define RGRID 128   // blocks in persistent recurrence kernel

// ---------------- device scratch ----------------
__device__ float         g_zx[(size_t)T_ * BB * N4];        // x@Wi + b, fp32
__device__ __nv_bfloat16 g_xhi[(size_t)T_ * BB * HH];
__device__ __nv_bfloat16 g_xlo[(size_t)T_ * BB * HH];
__device__ __nv_bfloat16 g_WiT_hi[(size_t)N4 * HH];         // [n][k]
__device__ __nv_bfloat16 g_WiT_lo[(size_t)N4 * HH];
__device__ __nv_bfloat16 g_WhT_hi[(size_t)N4 * HH];         // [n][k] (pack source)
__device__ __nv_bfloat16 g_WhT_lo[(size_t)N4 * HH];

// Fragment-order operands for the recurrence MMA (no smem staging):
// A (h): [buf 2][m(4)][kc(64)][lane(32)] uint4
__device__ uint4 g_hfrag_hi[2][4 * 64 * 32];
__device__ uint4 g_hfrag_lo[2][4 * 64 * 32];
// B (Wh): [bid(128)][nhalf(2)][kc(64)][lane(32)] uint4
__device__ uint4 g_whfrag_hi[(size_t)128 * 2 * 64 * 32];
__device__ uint4 g_whfrag_lo[(size_t)128 * 2 * 64 * 32];

// ---------------- grid barrier ----------------
__device__ unsigned int          g_bar_count = 0;
__device__ volatile unsigned int g_bar_gen   = 0;

__device__ __forceinline__ void grid_barrier()
{
    __syncthreads();
    if (threadIdx.x == 0) {
        __threadfence();
        unsigned int gen = g_bar_gen;
        if (atomicAdd(&g_bar_count, 1) == RGRID - 1) {
            g_bar_count = 0;
            __threadfence();
            g_bar_gen = gen + 1;
        } else {
            while (g_bar_gen == gen) __nanosleep(32);
        }
        __threadfence();
    }
    __syncthreads();
}

// ---------------- helpers ----------------
__device__ __forceinline__ void bsplit(float v, __nv_bfloat16& hi, __nv_bfloat16& lo)
{
    hi = __float2bfloat16(v);
    lo = __float2bfloat16(v - __bfloat162float(hi));
}

__device__ __forceinline__ float fast_sigmoid(float x)
{
    return __frcp_rn(1.f + __expf(-x));
}
__device__ __forceinline__ float fast_tanh(float x)
{
    return 1.f - 2.f * __frcp_rn(__expf(2.f * x) + 1.f);
}

__device__ __forceinline__ void mma16816(float c[4],
                                         uint32_t a0, uint32_t a1, uint32_t a2, uint32_t a3,
                                         uint32_t b0, uint32_t b1)
{
    asm("mma.sync.aligned.m16n8k16.row.col.f32.bf16.bf16.f32 "
        "{%0,%1,%2,%3}, {%4,%5,%6,%7}, {%8,%9}, {%0,%1,%2,%3};"
        : "+f"(c[0]), "+f"(c[1]), "+f"(c[2]), "+f"(c[3])
        : "r"(a0), "r"(a1), "r"(a2), "r"(a3), "r"(b0), "r"(b1));
}

// ---------------------------------------------------------------------------
// Fused prep kernel (launch 1). Sections by blockIdx.x:
//  [0, 8192)        : split-convert x -> g_xhi/g_xlo  (4 float4 per thread)
//  [8192, 12288)    : transpose+split Wi -> g_WiT_hi/lo
//  [12288, 16384)   : transpose+split Wh -> g_WhT_hi/lo
//  [16384, 16512)   : h0 -> fragment buffer 0
// ---------------------------------------------------------------------------
__global__ __launch_bounds__(256) void prep_fused(const float* __restrict__ x,
                                                  const float* __restrict__ Wi,
                                                  const float* __restrict__ Wh,
                                                  const float* __restrict__ h0)
{
    const int blk = blockIdx.x;
    const int tid = threadIdx.x;

    if (blk < 8192) {
        const float4* xv = (const float4*)x;
        __nv_bfloat162* dh = reinterpret_cast<__nv_bfloat162*>(g_xhi);
        __nv_bfloat162* dl = reinterpret_cast<__nv_bfloat162*>(g_xlo);
#pragma unroll
        for (int j = 0; j < 4; j++) {
            int i = blk * 256 + tid + j * (8192 * 256);
            float4 v = xv[i];
            __nv_bfloat16 h0b,l0b,h1b,l1b,h2b,l2b,h3b,l3b;
            bsplit(v.x,h0b,l0b); bsplit(v.y,h1b,l1b);
            bsplit(v.z,h2b,l2b); bsplit(v.w,h3b,l3b);
            __nv_bfloat162 a; a.x=h0b; a.y=h1b; dh[2*i]   = a;
            __nv_bfloat162 b; b.x=h2b; b.y=h3b; dh[2*i+1] = b;
            __nv_bfloat162 c; c.x=l0b; c.y=l1b; dl[2*i]   = c;
            __nv_bfloat162 d; d.x=l2b; d.y=l3b; dl[2*i+1] = d;
        }
    } else if (blk < 16384) {
        __shared__ float tile[32][33];
        int which = (blk >= 12288);
        int tt = blk - (which ? 12288 : 8192);           // 0..4095
        const float* src = which ? Wh : Wi;
        int gx = (tt & 127) * 32;                        // n
        int gy = (tt >> 7) * 32;                         // k
#pragma unroll
        for (int i = 0; i < 4; i++) {
            int idx = tid + i * 256;
            int kl = idx >> 5, col = idx & 31;
            tile[kl][col] = src[(size_t)(gy + kl) * N4 + gx + col];
        }
        __syncthreads();
        __nv_bfloat16* dh = which ? g_WhT_hi : g_WiT_hi;
        __nv_bfloat16* dl = which ? g_WhT_lo : g_WiT_lo;
#pragma unroll
        for (int i = 0; i < 4; i++) {
            int idx = tid + i * 256;
            int nl = idx >> 5, kc = idx & 31;
            float v = tile[kc][nl];
            __nv_bfloat16 h, l; bsplit(v, h, l);
            dh[(size_t)(gx + nl) * HH + gy + kc] = h;
            dl[(size_t)(gx + nl) * HH + gy + kc] = l;
        }
    } else {
        int idx = (blk - 16384) * 256 + tid;             // 0 .. 64*512-1
        int b_ = idx >> 9;
        int p  = idx & 511;
        float v0 = h0[b_ * HH + 2 * p];
        float v1 = h0[b_ * HH + 2 * p + 1];
        __nv_bfloat16 h0b,l0b,h1b,l1b;
        bsplit(v0,h0b,l0b); bsplit(v1,h1b,l1b);
        __nv_bfloat162 wh; wh.x=h0b; wh.y=h1b;
        __nv_bfloat162 wl; wl.x=l0b; wl.y=l1b;

        int kc = p >> 3, within = p & 7;
        int tq = within & 3, whi = within >> 2;
        int m = b_ >> 4, r16 = b_ & 15;
        int gq = r16 & 7, top = r16 >> 3;
        int lane = gq * 4 + tq;
        int w = whi * 2 + top;
        uint32_t off = (uint32_t)(((m * 64 + kc) * 32 + lane) * 4 + w);
        ((uint32_t*)g_hfrag_hi[0])[off] = *(uint32_t*)&wh;
        ((uint32_t*)g_hfrag_lo[0])[off] = *(uint32_t*)&wl;
    }
}

// ---------------------------------------------------------------------------
// Launch 2 (fused): blocks [0,8192) = phase-1 GEMM tiles; [8192,10240) = Wh
// fragment pack (reads g_WhT written by launch 1).
// ---------------------------------------------------------------------------
__global__ __launch_bounds__(256) void gemm_wx_pack(const float* __restrict__ bias)
{
    const int blk = blockIdx.x;
    const int tid = threadIdx.x;

    if (blk >= 8192) {
        int widx = (blk - 8192) * 256 + tid;             // 0 .. 524287
        int lane  = widx & 31;
        int kc    = (widx >> 5) & 63;
        int nhalf = (widx >> 11) & 1;
        int bidn  = widx >> 12;
        int gq = lane >> 2, tq = lane & 3;

        const uint32_t* WH = (const uint32_t*)g_WhT_hi;  // [col][512 pairs]
        const uint32_t* WL = (const uint32_t*)g_WhT_lo;
        uint32_t hi[4], lo[4];
#pragma unroll
        for (int w = 0; w < 4; w++) {
            int j = w >> 1, b = w & 1;
            int zc = nhalf * 16 + j * 8 + gq;
            int col = (zc >> 3) * 1024 + bidn * 8 + (zc & 7);
            int pair = kc * 8 + tq + b * 4;
            hi[w] = WH[(size_t)col * 512 + pair];
            lo[w] = WL[(size_t)col * 512 + pair];
        }
        g_whfrag_hi[widx] = make_uint4(hi[0], hi[1], hi[2], hi[3]);
        g_whfrag_lo[widx] = make_uint4(lo[0], lo[1], lo[2], lo[3]);
        return;
    }

    // ---- phase-1 GEMM: 128x128 tile, 8 warps, warp 64x32, kt=32 ----
    __shared__ uint32_t sAh[128 * 20], sAl[128 * 20];
    __shared__ uint32_t sBh[128 * 20], sBl[128 * 20];

    const uint32_t* Xh = (const uint32_t*)g_xhi;
    const uint32_t* Xl = (const uint32_t*)g_xlo;
    const uint32_t* Wh = (const uint32_t*)g_WiT_hi;
    const uint32_t* Wl = (const uint32_t*)g_WiT_lo;

    const int bn   = (blk & 31) * 128;
    const int bm   = (blk >> 5) * 128;
    const int lane = tid & 31, wp = tid >> 5;
    const int g    = lane >> 2, tq = lane & 3;
    const int wm   = (wp >> 2) * 64;
    const int wn   = (wp & 3) * 32;
    const int r0   = wp * 2 + (lane >> 4);
    const int kw   = lane & 15;

    float acc[4][4][4] = {};
    uint32_t pAh[8], pAl[8], pBh[8], pBl[8];

    auto LOAD = [&](int kc) {
        int k0w = kc * 16;
#pragma unroll
        for (int i = 0; i < 8; i++) {
            int row = r0 + 16 * i;
            size_t ga = (size_t)(bm + row) * 512 + k0w + kw;
            size_t gb = (size_t)(bn + row) * 512 + k0w + kw;
            pAh[i] = Xh[ga]; pAl[i] = Xl[ga];
            pBh[i] = Wh[gb]; pBl[i] = Wl[gb];
        }
    };
    auto STORE = [&]() {
#pragma unroll
        for (int i = 0; i < 8; i++) {
            int row = r0 + 16 * i;
            sAh[row * 20 + kw] = pAh[i]; sAl[row * 20 + kw] = pAl[i];
            sBh[row * 20 + kw] = pBh[i]; sBl[row * 20 + kw] = pBl[i];
        }
    };

    LOAD(0); STORE(); __syncthreads();

    for (int kc = 0; kc < 32; kc++) {
        if (kc < 31) LOAD(kc + 1);
#pragma unroll
        for (int s = 0; s < 2; s++) {
            int kwb = s * 8;
            uint32_t bh[4][2], bl[4][2];
#pragma unroll
            for (int nf = 0; nf < 4; nf++) {
                int base = (wn + nf * 8 + g) * 20 + kwb + tq;
                bh[nf][0] = sBh[base]; bh[nf][1] = sBh[base + 4];
                bl[nf][0] = sBl[base]; bl[nf][1] = sBl[base + 4];
            }
#pragma unroll
            for (int mf = 0; mf < 4; mf++) {
                int rb = (wm + mf * 16 + g) * 20 + kwb + tq;
                uint32_t a0 = sAh[rb], a1 = sAh[rb + 160];
                uint32_t a2 = sAh[rb + 4], a3 = sAh[rb + 164];
                uint32_t l0 = sAl[rb], l1 = sAl[rb + 160];
                uint32_t l2 = sAl[rb + 4], l3 = sAl[rb + 164];
                // term-major passes: per-acc order (hh, hl, lh) preserved,
                // dependency distance 4 instead of 1.
#pragma unroll
                for (int nf = 0; nf < 4; nf++)
                    mma16816(acc[mf][nf], a0, a1, a2, a3, bh[nf][0], bh[nf][1]);
#pragma unroll
                for (int nf = 0; nf < 4; nf++)
                    mma16816(acc[mf][nf], a0, a1, a2, a3, bl[nf][0], bl[nf][1]);
#pragma unroll
                for (int nf = 0; nf < 4; nf++)
                    mma16816(acc[mf][nf], l0, l1, l2, l3, bh[nf][0], bh[nf][1]);
            }
        }
        __syncthreads();
        if (kc < 31) { STORE(); __syncthreads(); }
    }

#pragma unroll
    for (int mf = 0; mf < 4; mf++) {
        int row0 = bm + wm + mf * 16 + g;
#pragma unroll
        for (int nf = 0; nf < 4; nf++) {
            int col = bn + wn + nf * 8 + tq * 2;
            float2 bb = *(const float2*)&bias[col];
            float2 v0, v1;
            v0.x = acc[mf][nf][0] + bb.x; v0.y = acc[mf][nf][1] + bb.y;
            v1.x = acc[mf][nf][2] + bb.x; v1.y = acc[mf][nf][3] + bb.y;
            *(float2*)&g_zx[(size_t)row0 * N4 + col]       = v0;
            *(float2*)&g_zx[(size_t)(row0 + 8) * N4 + col] = v1;
        }
    }
}

// ---------------------------------------------------------------------------
// Persistent recurrence (launch 3): 128 blocks x 256 thr.
// (ks in 4 K-quarters) x (mp in 2 m-halves); warp m32 x n32 over 16 k16
// chunks; 4-slot register pipeline. MMAs issued TERM-MAJOR across all 8
// accumulators (dependency distance 8) to avoid HMMA RAW chain stalls.
// ---------------------------------------------------------------------------
__global__ __launch_bounds__(256, 1)
void lstm_rec_mma(const float* __restrict__ c0,
                  float* __restrict__ ys,
                  float* __restrict__ cT,
                  float* __restrict__ hT)
{
    __shared__ float Zpart[6][1024];   // 24 KB: partials from ks=1..3, both mp
    __shared__ float Z[64][33];        // final z tile for pointwise gather

    const int tid  = threadIdx.x, bid = blockIdx.x;
    const int lane = tid & 31, wp = tid >> 5;
    const int gq   = lane >> 2, tq = lane & 3;
    const int ks   = wp & 3;           // K quarter: chunks [ks*16, ks*16+16)
    const int mp   = wp >> 2;          // m half: frags {2mp, 2mp+1}
    const int jb   = bid * 8;

    const uint4* WBh0 = g_whfrag_hi + ((size_t)(bid * 2 + 0) * 64) * 32;
    const uint4* WBl0 = g_whfrag_lo + ((size_t)(bid * 2 + 0) * 64) * 32;
    const uint4* WBh1 = g_whfrag_hi + ((size_t)(bid * 2 + 1) * 64) * 32;
    const uint4* WBl1 = g_whfrag_lo + ((size_t)(bid * 2 + 1) * 64) * 32;

    // pointwise decode
    const int pb  = tid >> 2;
    const int jj  = (tid & 3) * 2;
    const int j0  = jb + jj;
    const int p_g   = j0 >> 1;
    const int kcw   = p_g >> 3, within = p_g & 7;
    const int ptq   = within & 3, pwhi = within >> 2;
    const int pm    = pb >> 4, r16 = pb & 15;
    const int pg    = r16 & 7, ptop = r16 >> 3;
    const uint32_t hoff = (uint32_t)((((pm * 64 + kcw) * 32) + pg * 4 + ptq) * 4
                                     + pwhi * 2 + ptop);

    for (int t = 0; t < T_; t++) {
        const uint4* AH = g_hfrag_hi[t & 1];
        const uint4* AL = g_hfrag_lo[t & 1];

        // ---- prefetch pointwise operands ----
        const float* zx = g_zx + (size_t)t * BB * N4 + (size_t)pb * N4;
        const float* cp = (t == 0) ? c0 : cT;
        float2 xi = *(const float2*)&zx[j0];
        float2 xf = *(const float2*)&zx[HH + j0];
        float2 xg = *(const float2*)&zx[2 * HH + j0];
        float2 xo = *(const float2*)&zx[3 * HH + j0];
        float2 cv = *(const float2*)&cp[(size_t)pb * HH + j0];

        float acc[2][4][4];
#pragma unroll
        for (int a = 0; a < 2; a++)
#pragma unroll
            for (int b = 0; b < 4; b++)
#pragma unroll
                for (int r = 0; r < 4; r++) acc[a][b][r] = 0.f;

        // 4-slot pipeline: slot s holds chunk (i) with i % 4 == s
        uint4 aH[4][2], aL[4][2], bH[4][2], bL[4][2];
        const int kb = ks * 16;

        auto LOADC = [&](int i, int slot) {
            int off = (kb + i) * 32 + lane;
#pragma unroll
            for (int mm = 0; mm < 2; mm++) {
                aH[slot][mm] = AH[(2 * mp + mm) * 2048 + off];
                aL[slot][mm] = AL[(2 * mp + mm) * 2048 + off];
            }
            bH[slot][0] = WBh0[off]; bH[slot][1] = WBh1[off];
            bL[slot][0] = WBl0[off]; bL[slot][1] = WBl1[off];
        };

        LOADC(0, 0); LOADC(1, 1); LOADC(2, 2);

#pragma unroll 4
        for (int i = 0; i < 16; i++) {
            int cur = i & 3;
            if (i + 3 < 16) LOADC(i + 3, (i + 3) & 3);

            uint4 ah0 = aH[cur][0], ah1 = aH[cur][1];
            uint4 al0 = aL[cur][0], al1 = aL[cur][1];
            uint4 b0h = bH[cur][0], b1h = bH[cur][1];
            uint4 b0l = bL[cur][0], b1l = bL[cur][1];

            // pass 1: ah * bh  (8 independent accumulators)
            mma16816(acc[0][0], ah0.x, ah0.y, ah0.z, ah0.w, b0h.x, b0h.y);
            mma16816(acc[0][1], ah0.x, ah0.y, ah0.z, ah0.w, b0h.z, b0h.w);
            mma16816(acc[0][2], ah0.x, ah0.y, ah0.z, ah0.w, b1h.x, b1h.y);
            mma16816(acc[0][3], ah0.x, ah0.y, ah0.z, ah0.w, b1h.z, b1h.w);
            mma16816(acc[1][0], ah1.x, ah1.y, ah1.z, ah1.w, b0h.x, b0h.y);
            mma16816(acc[1][1], ah1.x, ah1.y, ah1.z, ah1.w, b0h.z, b0h.w);
            mma16816(acc[1][2], ah1.x, ah1.y, ah1.z, ah1.w, b1h.x, b1h.y);
            mma16816(acc[1][3], ah1.x, ah1.y, ah1.z, ah1.w, b1h.z, b1h.w);
            // pass 2: ah * bl
            mma16816(acc[0][0], ah0.x, ah0.y, ah0.z, ah0.w, b0l.x, b0l.y);
            mma16816(acc[0][1], ah0.x, ah0.y, ah0.z, ah0.w, b0l.z, b0l.w);
            mma16816(acc[0][2], ah0.x, ah0.y, ah0.z, ah0.w, b1l.x, b1l.y);
            mma16816(acc[0][3], ah0.x, ah0.y, ah0.z, ah0.w, b1l.z, b1l.w);
            mma16816(acc[1][0], ah1.x, ah1.y, ah1.z, ah1.w, b0l.x, b0l.y);
            mma16816(acc[1][1], ah1.x, ah1.y, ah1.z, ah1.w, b0l.z, b0l.w);
            mma16816(acc[1][2], ah1.x, ah1.y, ah1.z, ah1.w, b1l.x, b1l.y);
            mma16816(acc[1][3], ah1.x, ah1.y, ah1.z, ah1.w, b1l.z, b1l.w);
            // pass 3: al * bh
            mma16816(acc[0][0], al0.x, al0.y, al0.z, al0.w, b0h.x, b0h.y);
            mma16816(acc[0][1], al0.x, al0.y, al0.z, al0.w, b0h.z, b0h.w);
            mma16816(acc[0][2], al0.x, al0.y, al0.z, al0.w, b1h.x, b1h.y);
            mma16816(acc[0][3], al0.x, al0.y, al0.z, al0.w, b1h.z, b1h.w);
            mma16816(acc[1][0], al1.x, al1.y, al1.z, al1.w, b0h.x, b0h.y);
            mma16816(acc[1][1], al1.x, al1.y, al1.z, al1.w, b0h.z, b0h.w);
            mma16816(acc[1][2], al1.x, al1.y, al1.z, al1.w, b1h.x, b1h.y);
            mma16816(acc[1][3], al1.x, al1.y, al1.z, al1.w, b1h.z, b1h.w);
        }

        // ---- one-stage K-split reduction: ks=1..3 -> smem, ks=0 sums ----
        if (ks != 0) {
            float* zp = Zpart[mp * 3 + ks - 1];
#pragma unroll
            for (int mm = 0; mm < 2; mm++)
#pragma unroll
                for (int nf = 0; nf < 4; nf++)
#pragma unroll
                    for (int r = 0; r < 4; r++)
                        zp[((mm * 4 + nf) * 4 + r) * 32 + lane] = acc[mm][nf][r];
        }
        __syncthreads();
        if (ks == 0) {
#pragma unroll
            for (int s = 0; s < 3; s++) {
                const float* zp = Zpart[mp * 3 + s];
#pragma unroll
                for (int mm = 0; mm < 2; mm++)
#pragma unroll
                    for (int nf = 0; nf < 4; nf++)
#pragma unroll
                        for (int r = 0; r < 4; r++)
                            acc[mm][nf][r] += zp[((mm * 4 + nf) * 4 + r) * 32 + lane];
            }
#pragma unroll
            for (int mm = 0; mm < 2; mm++) {
                int row = mp * 32 + mm * 16 + gq;
#pragma unroll
                for (int nf = 0; nf < 4; nf++) {
                    int zb = (nf >> 1) * 16 + (nf & 1) * 8 + tq * 2;
                    Z[row][zb]         = acc[mm][nf][0];
                    Z[row][zb + 1]     = acc[mm][nf][1];
                    Z[row + 8][zb]     = acc[mm][nf][2];
                    Z[row + 8][zb + 1] = acc[mm][nf][3];
                }
            }
        }
        __syncthreads();

        // ---- pointwise gates ----
        {
            float* ys_t = ys + (size_t)t * BB * HH;
            uint32_t* nhh = (uint32_t*)g_hfrag_hi[(t + 1) & 1];
            uint32_t* nhl = (uint32_t*)g_hfrag_lo[(t + 1) & 1];

            float h2[2], c2[2];
#pragma unroll
            for (int e = 0; e < 2; e++) {
                int zc = jj + e;
                float zi = Z[pb][zc]      + (e ? xi.y : xi.x);
                float zf = Z[pb][8 + zc]  + (e ? xf.y : xf.x);
                float zg = Z[pb][16 + zc] + (e ? xg.y : xg.x);
                float zo = Z[pb][24 + zc] + (e ? xo.y : xo.x);

                float ig = fast_sigmoid(zi);
                float fg = fast_sigmoid(zf);
                float gg = fast_tanh(zg);
                float og = fast_sigmoid(zo);

                float cc = fg * (e ? cv.y : cv.x) + ig * gg;
                c2[e] = cc;
                h2[e] = og * fast_tanh(cc);
            }

            *(float2*)&cT[(size_t)pb * HH + j0]   = *(float2*)c2;
            *(float2*)&ys_t[(size_t)pb * HH + j0] = *(float2*)h2;
            if (t == T_ - 1) *(float2*)&hT[(size_t)pb * HH + j0] = *(float2*)h2;

            __nv_bfloat16 h0b,l0b,h1b,l1b;
            bsplit(h2[0], h0b, l0b); bsplit(h2[1], h1b, l1b);
            __nv_bfloat162 wh; wh.x = h0b; wh.y = h1b;
            __nv_bfloat162 wl; wl.x = l0b; wl.y = l1b;
            nhh[hoff] = *(uint32_t*)&wh;
            nhl[hoff] = *(uint32_t*)&wl;
        }

        grid_barrier();
    }
}

// ---------------------------------------------------------------------------
extern "C" void kernel_launch(void* const* d_in, const int* in_sizes, int n_in,
                              void* d_out, int out_size)
{
    const float* x  = (const float*)d_in[0];   // [T,B,D]
    const float* c0 = (const float*)d_in[1];   // [B,H]
    const float* h0 = (const float*)d_in[2];   // [B,H]
    const float* Wi = (const float*)d_in[3];   // [D,4H]
    const float* Wh = (const float*)d_in[4];   // [H,4H]
    const float* b  = (const float*)d_in[5];   // [4H]

    float* out = (float*)d_out;
    float* ys = out;                                  // [T,B,H]
    float* cT = out + (size_t)T_ * BB * HH;           // [B,H]
    float* hT = cT + (size_t)BB * HH;                 // [B,H]

    prep_fused<<<16512, 256>>>(x, Wi, Wh, h0);        // launch 1
    gemm_wx_pack<<<10240, 256>>>(b);                  // launch 2
    lstm_rec_mma<<<RGRID, 256>>>(c0, ys, cT, hT);     // launch 3
}

// round 13
// speedup vs baseline: 1.6458x; 1.0675x over previous
#include <cuda_runtime.h>
#include <cuda_bf16.h>
#include <cuda_fp16.h>
#include <math.h>
#include <stdint.h>

#define T_   512
#define BB   64
#define HH   1024
#define N4   4096
#define RGRID 128   // blocks in persistent recurrence kernel
#define WLO_SCALE   2048.0f
#define WLO_INV     (1.0f / 2048.0f)

// ---------------- device scratch ----------------
__device__ float         g_zx[(size_t)T_ * BB * N4];        // x@Wi + b, fp32
__device__ __nv_bfloat16 g_xhi[(size_t)T_ * BB * HH];
__device__ __nv_bfloat16 g_xlo[(size_t)T_ * BB * HH];
__device__ __nv_bfloat16 g_WiT_hi[(size_t)N4 * HH];         // [n][k] bf16 (phase-1)
__device__ __nv_bfloat16 g_WiT_lo[(size_t)N4 * HH];
__device__ __half        g_WhT_hi[(size_t)N4 * HH];         // [n][k] fp16 hi
__device__ __half        g_WhT_lo[(size_t)N4 * HH];         // fp16 (w-hi)*2048

// Fragment-order operands for the recurrence MMA:
// A (h, single fp16): [buf 2][m(4)][kc(64)][lane(32)] uint4
__device__ uint4 g_hfrag[2][4 * 64 * 32];
// B (Wh hi / lo_scaled): [bid(128)][nhalf(2)][kc(64)][lane(32)] uint4
__device__ uint4 g_whfrag_hi[(size_t)128 * 2 * 64 * 32];
__device__ uint4 g_whfrag_lo[(size_t)128 * 2 * 64 * 32];

// ---------------- tree grid barrier (8 groups x 16 blocks) ------------------
__device__ unsigned int          g_bar_grp[8 * 32];   // 128B-strided counters
__device__ unsigned int          g_bar_root = 0;
__device__ volatile unsigned int g_bar_gen  = 0;

__device__ __forceinline__ void grid_barrier()
{
    __syncthreads();
    if (threadIdx.x == 0) {
        __threadfence();
        unsigned int gen = g_bar_gen;
        int grp = blockIdx.x >> 4;                    // 16 blocks per group
        if (atomicAdd(&g_bar_grp[grp * 32], 1) == 15) {
            g_bar_grp[grp * 32] = 0;
            __threadfence();
            if (atomicAdd(&g_bar_root, 1) == 7) {
                g_bar_root = 0;
                __threadfence();
                g_bar_gen = gen + 1;
            }
        }
        while (g_bar_gen == gen) __nanosleep(32);
        __threadfence();
    }
    __syncthreads();
}

// ---------------- helpers ----------------
__device__ __forceinline__ void bsplit(float v, __nv_bfloat16& hi, __nv_bfloat16& lo)
{
    hi = __float2bfloat16(v);
    lo = __float2bfloat16(v - __bfloat162float(hi));
}

__device__ __forceinline__ float fast_sigmoid(float x)
{
    return __frcp_rn(1.f + __expf(-x));
}
__device__ __forceinline__ float fast_tanh(float x)
{
    return 1.f - 2.f * __frcp_rn(__expf(2.f * x) + 1.f);
}

// bf16 mma (phase 1)
__device__ __forceinline__ void mma16816(float c[4],
                                         uint32_t a0, uint32_t a1, uint32_t a2, uint32_t a3,
                                         uint32_t b0, uint32_t b1)
{
    asm("mma.sync.aligned.m16n8k16.row.col.f32.bf16.bf16.f32 "
        "{%0,%1,%2,%3}, {%4,%5,%6,%7}, {%8,%9}, {%0,%1,%2,%3};"
        : "+f"(c[0]), "+f"(c[1]), "+f"(c[2]), "+f"(c[3])
        : "r"(a0), "r"(a1), "r"(a2), "r"(a3), "r"(b0), "r"(b1));
}

// fp16 mma (recurrence)
__device__ __forceinline__ void mma16816h(float c[4],
                                          uint32_t a0, uint32_t a1, uint32_t a2, uint32_t a3,
                                          uint32_t b0, uint32_t b1)
{
    asm("mma.sync.aligned.m16n8k16.row.col.f32.f16.f16.f32 "
        "{%0,%1,%2,%3}, {%4,%5,%6,%7}, {%8,%9}, {%0,%1,%2,%3};"
        : "+f"(c[0]), "+f"(c[1]), "+f"(c[2]), "+f"(c[3])
        : "r"(a0), "r"(a1), "r"(a2), "r"(a3), "r"(b0), "r"(b1));
}

// ---------------------------------------------------------------------------
// Fused prep kernel (launch 1). Sections by blockIdx.x:
//  [0, 8192)        : split-convert x -> g_xhi/g_xlo (bf16, 4 float4/thread)
//  [8192, 12288)    : transpose+split Wi -> g_WiT_hi/lo (bf16)
//  [12288, 16384)   : transpose+split Wh -> g_WhT_hi/lo (fp16, lo*2048)
//  [16384, 16512)   : h0 -> fragment buffer 0 (fp16)
// ---------------------------------------------------------------------------
__global__ __launch_bounds__(256) void prep_fused(const float* __restrict__ x,
                                                  const float* __restrict__ Wi,
                                                  const float* __restrict__ Wh,
                                                  const float* __restrict__ h0)
{
    const int blk = blockIdx.x;
    const int tid = threadIdx.x;

    if (blk < 8192) {
        const float4* xv = (const float4*)x;
        __nv_bfloat162* dh = reinterpret_cast<__nv_bfloat162*>(g_xhi);
        __nv_bfloat162* dl = reinterpret_cast<__nv_bfloat162*>(g_xlo);
#pragma unroll
        for (int j = 0; j < 4; j++) {
            int i = blk * 256 + tid + j * (8192 * 256);
            float4 v = xv[i];
            __nv_bfloat16 h0b,l0b,h1b,l1b,h2b,l2b,h3b,l3b;
            bsplit(v.x,h0b,l0b); bsplit(v.y,h1b,l1b);
            bsplit(v.z,h2b,l2b); bsplit(v.w,h3b,l3b);
            __nv_bfloat162 a; a.x=h0b; a.y=h1b; dh[2*i]   = a;
            __nv_bfloat162 b; b.x=h2b; b.y=h3b; dh[2*i+1] = b;
            __nv_bfloat162 c; c.x=l0b; c.y=l1b; dl[2*i]   = c;
            __nv_bfloat162 d; d.x=l2b; d.y=l3b; dl[2*i+1] = d;
        }
    } else if (blk < 16384) {
        __shared__ float tile[32][33];
        int which = (blk >= 12288);
        int tt = blk - (which ? 12288 : 8192);           // 0..4095
        const float* src = which ? Wh : Wi;
        int gx = (tt & 127) * 32;                        // n
        int gy = (tt >> 7) * 32;                         // k
#pragma unroll
        for (int i = 0; i < 4; i++) {
            int idx = tid + i * 256;
            int kl = idx >> 5, col = idx & 31;
            tile[kl][col] = src[(size_t)(gy + kl) * N4 + gx + col];
        }
        __syncthreads();
        if (which == 0) {
#pragma unroll
            for (int i = 0; i < 4; i++) {
                int idx = tid + i * 256;
                int nl = idx >> 5, kc = idx & 31;
                float v = tile[kc][nl];
                __nv_bfloat16 h, l; bsplit(v, h, l);
                g_WiT_hi[(size_t)(gx + nl) * HH + gy + kc] = h;
                g_WiT_lo[(size_t)(gx + nl) * HH + gy + kc] = l;
            }
        } else {
#pragma unroll
            for (int i = 0; i < 4; i++) {
                int idx = tid + i * 256;
                int nl = idx >> 5, kc = idx & 31;
                float v = tile[kc][nl];
                __half h = __float2half(v);
                __half l = __float2half((v - __half2float(h)) * WLO_SCALE);
                g_WhT_hi[(size_t)(gx + nl) * HH + gy + kc] = h;
                g_WhT_lo[(size_t)(gx + nl) * HH + gy + kc] = l;
            }
        }
    } else {
        int idx = (blk - 16384) * 256 + tid;             // 0 .. 64*512-1
        int b_ = idx >> 9;
        int p  = idx & 511;
        float v0 = h0[b_ * HH + 2 * p];
        float v1 = h0[b_ * HH + 2 * p + 1];
        __half2 hv = __floats2half2_rn(v0, v1);

        int kc = p >> 3, within = p & 7;
        int tq = within & 3, whi = within >> 2;
        int m = b_ >> 4, r16 = b_ & 15;
        int gq = r16 & 7, top = r16 >> 3;
        int lane = gq * 4 + tq;
        int w = whi * 2 + top;
        uint32_t off = (uint32_t)(((m * 64 + kc) * 32 + lane) * 4 + w);
        ((uint32_t*)g_hfrag[0])[off] = *(uint32_t*)&hv;
    }
}

// ---------------------------------------------------------------------------
// Launch 2 (fused): blocks [0,8192) = phase-1 GEMM tiles (bf16 3-pass,
// term-major); [8192,10240) = Wh fp16 fragment pack.
// ---------------------------------------------------------------------------
__global__ __launch_bounds__(256) void gemm_wx_pack(const float* __restrict__ bias)
{
    const int blk = blockIdx.x;
    const int tid = threadIdx.x;

    if (blk >= 8192) {
        int widx = (blk - 8192) * 256 + tid;             // 0 .. 524287
        int lane  = widx & 31;
        int kc    = (widx >> 5) & 63;
        int nhalf = (widx >> 11) & 1;
        int bidn  = widx >> 12;
        int gq = lane >> 2, tq = lane & 3;

        const uint32_t* WH = (const uint32_t*)g_WhT_hi;  // [col][512 pairs]
        const uint32_t* WL = (const uint32_t*)g_WhT_lo;
        uint32_t hi[4], lo[4];
#pragma unroll
        for (int w = 0; w < 4; w++) {
            int j = w >> 1, b = w & 1;
            int zc = nhalf * 16 + j * 8 + gq;
            int col = (zc >> 3) * 1024 + bidn * 8 + (zc & 7);
            int pair = kc * 8 + tq + b * 4;
            hi[w] = WH[(size_t)col * 512 + pair];
            lo[w] = WL[(size_t)col * 512 + pair];
        }
        g_whfrag_hi[widx] = make_uint4(hi[0], hi[1], hi[2], hi[3]);
        g_whfrag_lo[widx] = make_uint4(lo[0], lo[1], lo[2], lo[3]);
        return;
    }

    // ---- phase-1 GEMM: 128x128 tile, 8 warps, warp 64x32, kt=32 ----
    __shared__ uint32_t sAh[128 * 20], sAl[128 * 20];
    __shared__ uint32_t sBh[128 * 20], sBl[128 * 20];

    const uint32_t* Xh = (const uint32_t*)g_xhi;
    const uint32_t* Xl = (const uint32_t*)g_xlo;
    const uint32_t* Wh = (const uint32_t*)g_WiT_hi;
    const uint32_t* Wl = (const uint32_t*)g_WiT_lo;

    const int bn   = (blk & 31) * 128;
    const int bm   = (blk >> 5) * 128;
    const int lane = tid & 31, wp = tid >> 5;
    const int g    = lane >> 2, tq = lane & 3;
    const int wm   = (wp >> 2) * 64;
    const int wn   = (wp & 3) * 32;
    const int r0   = wp * 2 + (lane >> 4);
    const int kw   = lane & 15;

    float acc[4][4][4] = {};
    uint32_t pAh[8], pAl[8], pBh[8], pBl[8];

    auto LOAD = [&](int kc) {
        int k0w = kc * 16;
#pragma unroll
        for (int i = 0; i < 8; i++) {
            int row = r0 + 16 * i;
            size_t ga = (size_t)(bm + row) * 512 + k0w + kw;
            size_t gb = (size_t)(bn + row) * 512 + k0w + kw;
            pAh[i] = Xh[ga]; pAl[i] = Xl[ga];
            pBh[i] = Wh[gb]; pBl[i] = Wl[gb];
        }
    };
    auto STORE = [&]() {
#pragma unroll
        for (int i = 0; i < 8; i++) {
            int row = r0 + 16 * i;
            sAh[row * 20 + kw] = pAh[i]; sAl[row * 20 + kw] = pAl[i];
            sBh[row * 20 + kw] = pBh[i]; sBl[row * 20 + kw] = pBl[i];
        }
    };

    LOAD(0); STORE(); __syncthreads();

    for (int kc = 0; kc < 32; kc++) {
        if (kc < 31) LOAD(kc + 1);
#pragma unroll
        for (int s = 0; s < 2; s++) {
            int kwb = s * 8;
            uint32_t bh[4][2], bl[4][2];
#pragma unroll
            for (int nf = 0; nf < 4; nf++) {
                int base = (wn + nf * 8 + g) * 20 + kwb + tq;
                bh[nf][0] = sBh[base]; bh[nf][1] = sBh[base + 4];
                bl[nf][0] = sBl[base]; bl[nf][1] = sBl[base + 4];
            }
#pragma unroll
            for (int mf = 0; mf < 4; mf++) {
                int rb = (wm + mf * 16 + g) * 20 + kwb + tq;
                uint32_t a0 = sAh[rb], a1 = sAh[rb + 160];
                uint32_t a2 = sAh[rb + 4], a3 = sAh[rb + 164];
                uint32_t l0 = sAl[rb], l1 = sAl[rb + 160];
                uint32_t l2 = sAl[rb + 4], l3 = sAl[rb + 164];
#pragma unroll
                for (int nf = 0; nf < 4; nf++)
                    mma16816(acc[mf][nf], a0, a1, a2, a3, bh[nf][0], bh[nf][1]);
#pragma unroll
                for (int nf = 0; nf < 4; nf++)
                    mma16816(acc[mf][nf], a0, a1, a2, a3, bl[nf][0], bl[nf][1]);
#pragma unroll
                for (int nf = 0; nf < 4; nf++)
                    mma16816(acc[mf][nf], l0, l1, l2, l3, bh[nf][0], bh[nf][1]);
            }
        }
        __syncthreads();
        if (kc < 31) { STORE(); __syncthreads(); }
    }

#pragma unroll
    for (int mf = 0; mf < 4; mf++) {
        int row0 = bm + wm + mf * 16 + g;
#pragma unroll
        for (int nf = 0; nf < 4; nf++) {
            int col = bn + wn + nf * 8 + tq * 2;
            float2 bb = *(const float2*)&bias[col];
            float2 v0, v1;
            v0.x = acc[mf][nf][0] + bb.x; v0.y = acc[mf][nf][1] + bb.y;
            v1.x = acc[mf][nf][2] + bb.x; v1.y = acc[mf][nf][3] + bb.y;
            *(float2*)&g_zx[(size_t)row0 * N4 + col]       = v0;
            *(float2*)&g_zx[(size_t)(row0 + 8) * N4 + col] = v1;
        }
    }
}

// ---------------------------------------------------------------------------
// Persistent recurrence (launch 3): 128 blocks x 256 thr.
// fp16 2-pass: z = h*W_hi + (h*W_lo_scaled)/2048, dual accumulators.
// (ks in 4 K-quarters) x (mp in 2 m-halves); warp m32 x n32 over 16 k16
// chunks; 4-slot register pipeline; one-stage smem reduction; tree barrier.
// ---------------------------------------------------------------------------
__global__ __launch_bounds__(256, 1)
void lstm_rec_mma(const float* __restrict__ c0,
                  float* __restrict__ ys,
                  float* __restrict__ cT,
                  float* __restrict__ hT)
{
    __shared__ float Zpart[6][1024];
    __shared__ float Z[64][33];

    const int tid  = threadIdx.x, bid = blockIdx.x;
    const int lane = tid & 31, wp = tid >> 5;
    const int gq   = lane >> 2, tq = lane & 3;
    const int ks   = wp & 3;
    const int mp   = wp >> 2;
    const int jb   = bid * 8;

    const uint4* WBh0 = g_whfrag_hi + ((size_t)(bid * 2 + 0) * 64) * 32;
    const uint4* WBl0 = g_whfrag_lo + ((size_t)(bid * 2 + 0) * 64) * 32;
    const uint4* WBh1 = g_whfrag_hi + ((size_t)(bid * 2 + 1) * 64) * 32;
    const uint4* WBl1 = g_whfrag_lo + ((size_t)(bid * 2 + 1) * 64) * 32;

    // pointwise decode
    const int pb  = tid >> 2;
    const int jj  = (tid & 3) * 2;
    const int j0  = jb + jj;
    const int p_g   = j0 >> 1;
    const int kcw   = p_g >> 3, within = p_g & 7;
    const int ptq   = within & 3, pwhi = within >> 2;
    const int pm    = pb >> 4, r16 = pb & 15;
    const int pg    = r16 & 7, ptop = r16 >> 3;
    const uint32_t hoff = (uint32_t)((((pm * 64 + kcw) * 32) + pg * 4 + ptq) * 4
                                     + pwhi * 2 + ptop);

    for (int t = 0; t < T_; t++) {
        const uint4* AF = g_hfrag[t & 1];

        // ---- prefetch pointwise operands ----
        const float* zx = g_zx + (size_t)t * BB * N4 + (size_t)pb * N4;
        const float* cp = (t == 0) ? c0 : cT;
        float2 xi = *(const float2*)&zx[j0];
        float2 xf = *(const float2*)&zx[HH + j0];
        float2 xg = *(const float2*)&zx[2 * HH + j0];
        float2 xo = *(const float2*)&zx[3 * HH + j0];
        float2 cv = *(const float2*)&cp[(size_t)pb * HH + j0];

        float accH[2][4][4], accL[2][4][4];
#pragma unroll
        for (int a = 0; a < 2; a++)
#pragma unroll
            for (int b = 0; b < 4; b++)
#pragma unroll
                for (int r = 0; r < 4; r++) { accH[a][b][r] = 0.f; accL[a][b][r] = 0.f; }

        // 4-slot pipeline
        uint4 aF[4][2], bH[4][2], bL[4][2];
        const int kb = ks * 16;

        auto LOADC = [&](int i, int slot) {
            int off = (kb + i) * 32 + lane;
#pragma unroll
            for (int mm = 0; mm < 2; mm++)
                aF[slot][mm] = AF[(2 * mp + mm) * 2048 + off];
            bH[slot][0] = WBh0[off]; bH[slot][1] = WBh1[off];
            bL[slot][0] = WBl0[off]; bL[slot][1] = WBl1[off];
        };

        LOADC(0, 0); LOADC(1, 1); LOADC(2, 2);

#pragma unroll 4
        for (int i = 0; i < 16; i++) {
            int cur = i & 3;
            if (i + 3 < 16) LOADC(i + 3, (i + 3) & 3);

            uint4 a0 = aF[cur][0], a1 = aF[cur][1];
            uint4 b0h = bH[cur][0], b1h = bH[cur][1];
            uint4 b0l = bL[cur][0], b1l = bL[cur][1];

            // pass 1: h * W_hi  -> accH (8 independent accumulators)
            mma16816h(accH[0][0], a0.x, a0.y, a0.z, a0.w, b0h.x, b0h.y);
            mma16816h(accH[0][1], a0.x, a0.y, a0.z, a0.w, b0h.z, b0h.w);
            mma16816h(accH[0][2], a0.x, a0.y, a0.z, a0.w, b1h.x, b1h.y);
            mma16816h(accH[0][3], a0.x, a0.y, a0.z, a0.w, b1h.z, b1h.w);
            mma16816h(accH[1][0], a1.x, a1.y, a1.z, a1.w, b0h.x, b0h.y);
            mma16816h(accH[1][1], a1.x, a1.y, a1.z, a1.w, b0h.z, b0h.w);
            mma16816h(accH[1][2], a1.x, a1.y, a1.z, a1.w, b1h.x, b1h.y);
            mma16816h(accH[1][3], a1.x, a1.y, a1.z, a1.w, b1h.z, b1h.w);
            // pass 2: h * W_lo_scaled -> accL
            mma16816h(accL[0][0], a0.x, a0.y, a0.z, a0.w, b0l.x, b0l.y);
            mma16816h(accL[0][1], a0.x, a0.y, a0.z, a0.w, b0l.z, b0l.w);
            mma16816h(accL[0][2], a0.x, a0.y, a0.z, a0.w, b1l.x, b1l.y);
            mma16816h(accL[0][3], a0.x, a0.y, a0.z, a0.w, b1l.z, b1l.w);
            mma16816h(accL[1][0], a1.x, a1.y, a1.z, a1.w, b0l.x, b0l.y);
            mma16816h(accL[1][1], a1.x, a1.y, a1.z, a1.w, b0l.z, b0l.w);
            mma16816h(accL[1][2], a1.x, a1.y, a1.z, a1.w, b1l.x, b1l.y);
            mma16816h(accL[1][3], a1.x, a1.y, a1.z, a1.w, b1l.z, b1l.w);
        }

        // combine: z = accH + accL/2048
#pragma unroll
        for (int mm = 0; mm < 2; mm++)
#pragma unroll
            for (int nf = 0; nf < 4; nf++)
#pragma unroll
                for (int r = 0; r < 4; r++)
                    accH[mm][nf][r] = fmaf(accL[mm][nf][r], WLO_INV, accH[mm][nf][r]);

        // ---- one-stage K-split reduction: ks=1..3 -> smem, ks=0 sums ----
        if (ks != 0) {
            float* zp = Zpart[mp * 3 + ks - 1];
#pragma unroll
            for (int mm = 0; mm < 2; mm++)
#pragma unroll
                for (int nf = 0; nf < 4; nf++)
#pragma unroll
                    for (int r = 0; r < 4; r++)
                        zp[((mm * 4 + nf) * 4 + r) * 32 + lane] = accH[mm][nf][r];
        }
        __syncthreads();
        if (ks == 0) {
#pragma unroll
            for (int s = 0; s < 3; s++) {
                const float* zp = Zpart[mp * 3 + s];
#pragma unroll
                for (int mm = 0; mm < 2; mm++)
#pragma unroll
                    for (int nf = 0; nf < 4; nf++)
#pragma unroll
                        for (int r = 0; r < 4; r++)
                            accH[mm][nf][r] += zp[((mm * 4 + nf) * 4 + r) * 32 + lane];
            }
#pragma unroll
            for (int mm = 0; mm < 2; mm++) {
                int row = mp * 32 + mm * 16 + gq;
#pragma unroll
                for (int nf = 0; nf < 4; nf++) {
                    int zb = (nf >> 1) * 16 + (nf & 1) * 8 + tq * 2;
                    Z[row][zb]         = accH[mm][nf][0];
                    Z[row][zb + 1]     = accH[mm][nf][1];
                    Z[row + 8][zb]     = accH[mm][nf][2];
                    Z[row + 8][zb + 1] = accH[mm][nf][3];
                }
            }
        }
        __syncthreads();

        // ---- pointwise gates ----
        {
            float* ys_t = ys + (size_t)t * BB * HH;
            uint32_t* nh = (uint32_t*)g_hfrag[(t + 1) & 1];

            float h2[2], c2[2];
#pragma unroll
            for (int e = 0; e < 2; e++) {
                int zc = jj + e;
                float zi = Z[pb][zc]      + (e ? xi.y : xi.x);
                float zf = Z[pb][8 + zc]  + (e ? xf.y : xf.x);
                float zg = Z[pb][16 + zc] + (e ? xg.y : xg.x);
                float zo = Z[pb][24 + zc] + (e ? xo.y : xo.x);

                float ig = fast_sigmoid(zi);
                float fg = fast_sigmoid(zf);
                float gg = fast_tanh(zg);
                float og = fast_sigmoid(zo);

                float cc = fg * (e ? cv.y : cv.x) + ig * gg;
                c2[e] = cc;
                h2[e] = og * fast_tanh(cc);
            }

            *(float2*)&cT[(size_t)pb * HH + j0]   = *(float2*)c2;
            *(float2*)&ys_t[(size_t)pb * HH + j0] = *(float2*)h2;
            if (t == T_ - 1) *(float2*)&hT[(size_t)pb * HH + j0] = *(float2*)h2;

            __half2 hv = __floats2half2_rn(h2[0], h2[1]);
            nh[hoff] = *(uint32_t*)&hv;
        }

        grid_barrier();
    }
}

// ---------------------------------------------------------------------------
extern "C" void kernel_launch(void* const* d_in, const int* in_sizes, int n_in,
                              void* d_out, int out_size)
{
    const float* x  = (const float*)d_in[0];   // [T,B,D]
    const float* c0 = (const float*)d_in[1];   // [B,H]
    const float* h0 = (const float*)d_in[2];   // [B,H]
    const float* Wi = (const float*)d_in[3];   // [D,4H]
    const float* Wh = (const float*)d_in[4];   // [H,4H]
    const float* b  = (const float*)d_in[5];   // [4H]

    float* out = (float*)d_out;
    float* ys = out;                                  // [T,B,H]
    float* cT = out + (size_t)T_ * BB * HH;           // [B,H]
    float* hT = cT + (size_t)BB * HH;                 // [B,H]

    prep_fused<<<16512, 256>>>(x, Wi, Wh, h0);        // launch 1
    gemm_wx_pack<<<10240, 256>>>(b);                  // launch 2
    lstm_rec_mma<<<RGRID, 256>>>(c0, ys, cT, hT);     // launch 3
}

// round 14
// speedup vs baseline: 1.9841x; 1.2055x over previous
#include <cuda_runtime.h>
#include <cuda_bf16.h>
#include <cuda_fp16.h>
#include <math.h>
#include <stdint.h>

#define T_   512
#define BB   64
#define HH   1024
#define N4   4096
#define RGRID 128   // blocks in persistent recurrence kernel
#define WLO_SCALE   2048.0f
#define WLO_INV     (1.0f / 2048.0f)

// ---------------- device scratch ----------------
__device__ float  g_zx[(size_t)T_ * BB * N4];        // x@Wi + b, fp32
__device__ __half g_xh[(size_t)T_ * BB * HH];        // x, single fp16
__device__ __half g_WiT_h[(size_t)N4 * HH];          // [n][k] fp16 hi
__device__ __half g_WiT_l[(size_t)N4 * HH];          // fp16 lo (unscaled, subnormal)
__device__ __half g_WhT_hi[(size_t)N4 * HH];         // [n][k] fp16 hi
__device__ __half g_WhT_lo[(size_t)N4 * HH];         // fp16 (w-hi)*2048

// Fragment-order operands for the recurrence MMA:
// A (h, single fp16): [buf 2][m(4)][kc(64)][lane(32)] uint4
__device__ uint4 g_hfrag[2][4 * 64 * 32];
// B (Wh hi / lo_scaled): [bid(128)][nhalf(2)][kc(64)][lane(32)] uint4
__device__ uint4 g_whfrag_hi[(size_t)128 * 2 * 64 * 32];
__device__ uint4 g_whfrag_lo[(size_t)128 * 2 * 64 * 32];

// ---------------- tree grid barrier (8 groups x 16 blocks) ------------------
__device__ unsigned int          g_bar_grp[8 * 32];   // 128B-strided counters
__device__ unsigned int          g_bar_root = 0;
__device__ volatile unsigned int g_bar_gen  = 0;

__device__ __forceinline__ void grid_barrier()
{
    __syncthreads();
    if (threadIdx.x == 0) {
        __threadfence();
        unsigned int gen = g_bar_gen;
        int grp = blockIdx.x >> 4;                    // 16 blocks per group
        if (atomicAdd(&g_bar_grp[grp * 32], 1) == 15) {
            g_bar_grp[grp * 32] = 0;
            __threadfence();
            if (atomicAdd(&g_bar_root, 1) == 7) {
                g_bar_root = 0;
                __threadfence();
                g_bar_gen = gen + 1;
            }
        }
        while (g_bar_gen == gen) __nanosleep(32);
        __threadfence();
    }
    __syncthreads();
}

// ---------------- helpers ----------------
__device__ __forceinline__ float fast_sigmoid(float x)
{
    return __frcp_rn(1.f + __expf(-x));
}
__device__ __forceinline__ float fast_tanh(float x)
{
    return 1.f - 2.f * __frcp_rn(__expf(2.f * x) + 1.f);
}

// fp16 mma
__device__ __forceinline__ void mma16816h(float c[4],
                                          uint32_t a0, uint32_t a1, uint32_t a2, uint32_t a3,
                                          uint32_t b0, uint32_t b1)
{
    asm("mma.sync.aligned.m16n8k16.row.col.f32.f16.f16.f32 "
        "{%0,%1,%2,%3}, {%4,%5,%6,%7}, {%8,%9}, {%0,%1,%2,%3};"
        : "+f"(c[0]), "+f"(c[1]), "+f"(c[2]), "+f"(c[3])
        : "r"(a0), "r"(a1), "r"(a2), "r"(a3), "r"(b0), "r"(b1));
}

// ---------------------------------------------------------------------------
// Fused prep kernel (launch 1). Sections by blockIdx.x:
//  [0, 8192)        : convert x -> g_xh (fp16, 4 float4/thread)
//  [8192, 12288)    : transpose+split Wi -> g_WiT_h/l (fp16, lo unscaled)
//  [12288, 16384)   : transpose+split Wh -> g_WhT_hi/lo (fp16, lo*2048)
//  [16384, 16512)   : h0 -> fragment buffer 0 (fp16)
// ---------------------------------------------------------------------------
__global__ __launch_bounds__(256) void prep_fused(const float* __restrict__ x,
                                                  const float* __restrict__ Wi,
                                                  const float* __restrict__ Wh,
                                                  const float* __restrict__ h0)
{
    const int blk = blockIdx.x;
    const int tid = threadIdx.x;

    if (blk < 8192) {
        const float4* xv = (const float4*)x;
        __half2* dx = reinterpret_cast<__half2*>(g_xh);
#pragma unroll
        for (int j = 0; j < 4; j++) {
            int i = blk * 256 + tid + j * (8192 * 256);
            float4 v = xv[i];
            dx[2 * i]     = __floats2half2_rn(v.x, v.y);
            dx[2 * i + 1] = __floats2half2_rn(v.z, v.w);
        }
    } else if (blk < 16384) {
        __shared__ float tile[32][33];
        int which = (blk >= 12288);
        int tt = blk - (which ? 12288 : 8192);           // 0..4095
        const float* src = which ? Wh : Wi;
        int gx = (tt & 127) * 32;                        // n
        int gy = (tt >> 7) * 32;                         // k
#pragma unroll
        for (int i = 0; i < 4; i++) {
            int idx = tid + i * 256;
            int kl = idx >> 5, col = idx & 31;
            tile[kl][col] = src[(size_t)(gy + kl) * N4 + gx + col];
        }
        __syncthreads();
        if (which == 0) {
#pragma unroll
            for (int i = 0; i < 4; i++) {
                int idx = tid + i * 256;
                int nl = idx >> 5, kc = idx & 31;
                float v = tile[kc][nl];
                __half h = __float2half(v);
                __half l = __float2half(v - __half2float(h));   // subnormal ok
                g_WiT_h[(size_t)(gx + nl) * HH + gy + kc] = h;
                g_WiT_l[(size_t)(gx + nl) * HH + gy + kc] = l;
            }
        } else {
#pragma unroll
            for (int i = 0; i < 4; i++) {
                int idx = tid + i * 256;
                int nl = idx >> 5, kc = idx & 31;
                float v = tile[kc][nl];
                __half h = __float2half(v);
                __half l = __float2half((v - __half2float(h)) * WLO_SCALE);
                g_WhT_hi[(size_t)(gx + nl) * HH + gy + kc] = h;
                g_WhT_lo[(size_t)(gx + nl) * HH + gy + kc] = l;
            }
        }
    } else {
        int idx = (blk - 16384) * 256 + tid;             // 0 .. 64*512-1
        int b_ = idx >> 9;
        int p  = idx & 511;
        float v0 = h0[b_ * HH + 2 * p];
        float v1 = h0[b_ * HH + 2 * p + 1];
        __half2 hv = __floats2half2_rn(v0, v1);

        int kc = p >> 3, within = p & 7;
        int tq = within & 3, whi = within >> 2;
        int m = b_ >> 4, r16 = b_ & 15;
        int gq = r16 & 7, top = r16 >> 3;
        int lane = gq * 4 + tq;
        int w = whi * 2 + top;
        uint32_t off = (uint32_t)(((m * 64 + kc) * 32 + lane) * 4 + w);
        ((uint32_t*)g_hfrag[0])[off] = *(uint32_t*)&hv;
    }
}

// ---------------------------------------------------------------------------
// Launch 2 (fused): blocks [0,8192) = phase-1 GEMM tiles (fp16 2-pass,
// single accumulator); [8192,10240) = Wh fp16 fragment pack.
// ---------------------------------------------------------------------------
__global__ __launch_bounds__(256) void gemm_wx_pack(const float* __restrict__ bias)
{
    const int blk = blockIdx.x;
    const int tid = threadIdx.x;

    if (blk >= 8192) {
        int widx = (blk - 8192) * 256 + tid;             // 0 .. 524287
        int lane  = widx & 31;
        int kc    = (widx >> 5) & 63;
        int nhalf = (widx >> 11) & 1;
        int bidn  = widx >> 12;
        int gq = lane >> 2, tq = lane & 3;

        const uint32_t* WH = (const uint32_t*)g_WhT_hi;  // [col][512 pairs]
        const uint32_t* WL = (const uint32_t*)g_WhT_lo;
        uint32_t hi[4], lo[4];
#pragma unroll
        for (int w = 0; w < 4; w++) {
            int j = w >> 1, b = w & 1;
            int zc = nhalf * 16 + j * 8 + gq;
            int col = (zc >> 3) * 1024 + bidn * 8 + (zc & 7);
            int pair = kc * 8 + tq + b * 4;
            hi[w] = WH[(size_t)col * 512 + pair];
            lo[w] = WL[(size_t)col * 512 + pair];
        }
        g_whfrag_hi[widx] = make_uint4(hi[0], hi[1], hi[2], hi[3]);
        g_whfrag_lo[widx] = make_uint4(lo[0], lo[1], lo[2], lo[3]);
        return;
    }

    // ---- phase-1 GEMM: 128x128 tile, 8 warps, warp 64x32, kt=32, fp16 ----
    __shared__ uint32_t sA[128 * 20], sBh[128 * 20], sBl[128 * 20];

    const uint32_t* Xp = (const uint32_t*)g_xh;
    const uint32_t* Wh = (const uint32_t*)g_WiT_h;
    const uint32_t* Wl = (const uint32_t*)g_WiT_l;

    const int bn   = (blk & 31) * 128;
    const int bm   = (blk >> 5) * 128;
    const int lane = tid & 31, wp = tid >> 5;
    const int g    = lane >> 2, tq = lane & 3;
    const int wm   = (wp >> 2) * 64;
    const int wn   = (wp & 3) * 32;
    const int r0   = wp * 2 + (lane >> 4);
    const int kw   = lane & 15;

    float acc[4][4][4] = {};
    uint32_t pA[8], pBh[8], pBl[8];

    auto LOAD = [&](int kc) {
        int k0w = kc * 16;
#pragma unroll
        for (int i = 0; i < 8; i++) {
            int row = r0 + 16 * i;
            size_t ga = (size_t)(bm + row) * 512 + k0w + kw;
            size_t gb = (size_t)(bn + row) * 512 + k0w + kw;
            pA[i] = Xp[ga]; pBh[i] = Wh[gb]; pBl[i] = Wl[gb];
        }
    };
    auto STORE = [&]() {
#pragma unroll
        for (int i = 0; i < 8; i++) {
            int row = r0 + 16 * i;
            sA[row * 20 + kw]  = pA[i];
            sBh[row * 20 + kw] = pBh[i];
            sBl[row * 20 + kw] = pBl[i];
        }
    };

    LOAD(0); STORE(); __syncthreads();

    for (int kc = 0; kc < 32; kc++) {
        if (kc < 31) LOAD(kc + 1);
#pragma unroll
        for (int s = 0; s < 2; s++) {
            int kwb = s * 8;
            uint32_t bh[4][2], bl[4][2];
#pragma unroll
            for (int nf = 0; nf < 4; nf++) {
                int base = (wn + nf * 8 + g) * 20 + kwb + tq;
                bh[nf][0] = sBh[base]; bh[nf][1] = sBh[base + 4];
                bl[nf][0] = sBl[base]; bl[nf][1] = sBl[base + 4];
            }
#pragma unroll
            for (int mf = 0; mf < 4; mf++) {
                int rb = (wm + mf * 16 + g) * 20 + kwb + tq;
                uint32_t a0 = sA[rb], a1 = sA[rb + 160];
                uint32_t a2 = sA[rb + 4], a3 = sA[rb + 164];
#pragma unroll
                for (int nf = 0; nf < 4; nf++)
                    mma16816h(acc[mf][nf], a0, a1, a2, a3, bh[nf][0], bh[nf][1]);
#pragma unroll
                for (int nf = 0; nf < 4; nf++)
                    mma16816h(acc[mf][nf], a0, a1, a2, a3, bl[nf][0], bl[nf][1]);
            }
        }
        __syncthreads();
        if (kc < 31) { STORE(); __syncthreads(); }
    }

#pragma unroll
    for (int mf = 0; mf < 4; mf++) {
        int row0 = bm + wm + mf * 16 + g;
#pragma unroll
        for (int nf = 0; nf < 4; nf++) {
            int col = bn + wn + nf * 8 + tq * 2;
            float2 bb = *(const float2*)&bias[col];
            float2 v0, v1;
            v0.x = acc[mf][nf][0] + bb.x; v0.y = acc[mf][nf][1] + bb.y;
            v1.x = acc[mf][nf][2] + bb.x; v1.y = acc[mf][nf][3] + bb.y;
            *(float2*)&g_zx[(size_t)row0 * N4 + col]       = v0;
            *(float2*)&g_zx[(size_t)(row0 + 8) * N4 + col] = v1;
        }
    }
}

// ---------------------------------------------------------------------------
// Persistent recurrence (launch 3): 128 blocks x 256 thr.
// Wh fragments resident in dynamic smem (loaded once, reused 512 steps);
// per-step global loads = A (h-frags) only. fp16 2-pass, dual accumulators.
// ---------------------------------------------------------------------------
#define REC_SB_U4   8192                     // 8192 uint4 = 128 KB
#define REC_SMEM    (131072 + 24576 + 8448)  // sB + Zpart + Z

__global__ __launch_bounds__(256, 1)
void lstm_rec_mma(const float* __restrict__ c0,
                  float* __restrict__ ys,
                  float* __restrict__ cT,
                  float* __restrict__ hT)
{
    extern __shared__ char dsm[];
    uint4* sB = (uint4*)dsm;                               // [hl(2)][nhalf(2)][kc64][lane32]
    float* Zpart = (float*)(dsm + 131072);                 // 6 * 1024
    float (*Z)[33] = (float(*)[33])(dsm + 131072 + 24576); // 64 x 33

    const int tid  = threadIdx.x, bid = blockIdx.x;
    const int lane = tid & 31, wp = tid >> 5;
    const int gq   = lane >> 2, tq = lane & 3;
    const int ks   = wp & 3;
    const int mp   = wp >> 2;
    const int jb   = bid * 8;

    // ---- load this block's Wh fragments into smem (once) ----
    {
        const uint4* GH = g_whfrag_hi + (size_t)bid * 4096;
        const uint4* GL = g_whfrag_lo + (size_t)bid * 4096;
#pragma unroll
        for (int i = 0; i < 16; i++) sB[tid + i * 256]        = GH[tid + i * 256];
#pragma unroll
        for (int i = 0; i < 16; i++) sB[4096 + tid + i * 256] = GL[tid + i * 256];
    }
    __syncthreads();

    // pointwise decode
    const int pb  = tid >> 2;
    const int jj  = (tid & 3) * 2;
    const int j0  = jb + jj;
    const int p_g   = j0 >> 1;
    const int kcw   = p_g >> 3, within = p_g & 7;
    const int ptq   = within & 3, pwhi = within >> 2;
    const int pm    = pb >> 4, r16 = pb & 15;
    const int pg    = r16 & 7, ptop = r16 >> 3;
    const uint32_t hoff = (uint32_t)((((pm * 64 + kcw) * 32) + pg * 4 + ptq) * 4
                                     + pwhi * 2 + ptop);

    for (int t = 0; t < T_; t++) {
        const uint4* AF = g_hfrag[t & 1];

        // ---- prefetch pointwise operands ----
        const float* zx = g_zx + (size_t)t * BB * N4 + (size_t)pb * N4;
        const float* cp = (t == 0) ? c0 : cT;
        float2 xi = *(const float2*)&zx[j0];
        float2 xf = *(const float2*)&zx[HH + j0];
        float2 xg = *(const float2*)&zx[2 * HH + j0];
        float2 xo = *(const float2*)&zx[3 * HH + j0];
        float2 cv = *(const float2*)&cp[(size_t)pb * HH + j0];

        float accH[2][4][4], accL[2][4][4];
#pragma unroll
        for (int a = 0; a < 2; a++)
#pragma unroll
            for (int b = 0; b < 4; b++)
#pragma unroll
                for (int r = 0; r < 4; r++) { accH[a][b][r] = 0.f; accL[a][b][r] = 0.f; }

        // 4-slot pipeline for A (global); B read from smem per-iteration
        uint4 aF[4][2];
        const int kb = ks * 16;

        auto LOADA = [&](int i, int slot) {
            int off = (kb + i) * 32 + lane;
#pragma unroll
            for (int mm = 0; mm < 2; mm++)
                aF[slot][mm] = AF[(2 * mp + mm) * 2048 + off];
        };

        LOADA(0, 0); LOADA(1, 1); LOADA(2, 2);

#pragma unroll 4
        for (int i = 0; i < 16; i++) {
            int cur = i & 3;
            if (i + 3 < 16) LOADA(i + 3, (i + 3) & 3);

            int off = (kb + i) * 32 + lane;
            uint4 b0h = sB[off],        b1h = sB[2048 + off];
            uint4 b0l = sB[4096 + off], b1l = sB[6144 + off];
            uint4 a0 = aF[cur][0], a1 = aF[cur][1];

            // pass 1: h * W_hi  -> accH
            mma16816h(accH[0][0], a0.x, a0.y, a0.z, a0.w, b0h.x, b0h.y);
            mma16816h(accH[0][1], a0.x, a0.y, a0.z, a0.w, b0h.z, b0h.w);
            mma16816h(accH[0][2], a0.x, a0.y, a0.z, a0.w, b1h.x, b1h.y);
            mma16816h(accH[0][3], a0.x, a0.y, a0.z, a0.w, b1h.z, b1h.w);
            mma16816h(accH[1][0], a1.x, a1.y, a1.z, a1.w, b0h.x, b0h.y);
            mma16816h(accH[1][1], a1.x, a1.y, a1.z, a1.w, b0h.z, b0h.w);
            mma16816h(accH[1][2], a1.x, a1.y, a1.z, a1.w, b1h.x, b1h.y);
            mma16816h(accH[1][3], a1.x, a1.y, a1.z, a1.w, b1h.z, b1h.w);
            // pass 2: h * W_lo_scaled -> accL
            mma16816h(accL[0][0], a0.x, a0.y, a0.z, a0.w, b0l.x, b0l.y);
            mma16816h(accL[0][1], a0.x, a0.y, a0.z, a0.w, b0l.z, b0l.w);
            mma16816h(accL[0][2], a0.x, a0.y, a0.z, a0.w, b1l.x, b1l.y);
            mma16816h(accL[0][3], a0.x, a0.y, a0.z, a0.w, b1l.z, b1l.w);
            mma16816h(accL[1][0], a1.x, a1.y, a1.z, a1.w, b0l.x, b0l.y);
            mma16816h(accL[1][1], a1.x, a1.y, a1.z, a1.w, b0l.z, b0l.w);
            mma16816h(accL[1][2], a1.x, a1.y, a1.z, a1.w, b1l.x, b1l.y);
            mma16816h(accL[1][3], a1.x, a1.y, a1.z, a1.w, b1l.z, b1l.w);
        }

        // combine: z = accH + accL/2048
#pragma unroll
        for (int mm = 0; mm < 2; mm++)
#pragma unroll
            for (int nf = 0; nf < 4; nf++)
#pragma unroll
                for (int r = 0; r < 4; r++)
                    accH[mm][nf][r] = fmaf(accL[mm][nf][r], WLO_INV, accH[mm][nf][r]);

        // ---- one-stage K-split reduction: ks=1..3 -> smem, ks=0 sums ----
        if (ks != 0) {
            float* zp = Zpart + (mp * 3 + ks - 1) * 1024;
#pragma unroll
            for (int mm = 0; mm < 2; mm++)
#pragma unroll
                for (int nf = 0; nf < 4; nf++)
#pragma unroll
                    for (int r = 0; r < 4; r++)
                        zp[((mm * 4 + nf) * 4 + r) * 32 + lane] = accH[mm][nf][r];
        }
        __syncthreads();
        if (ks == 0) {
#pragma unroll
            for (int s = 0; s < 3; s++) {
                const float* zp = Zpart + (mp * 3 + s) * 1024;
#pragma unroll
                for (int mm = 0; mm < 2; mm++)
#pragma unroll
                    for (int nf = 0; nf < 4; nf++)
#pragma unroll
                        for (int r = 0; r < 4; r++)
                            accH[mm][nf][r] += zp[((mm * 4 + nf) * 4 + r) * 32 + lane];
            }
#pragma unroll
            for (int mm = 0; mm < 2; mm++) {
                int row = mp * 32 + mm * 16 + gq;
#pragma unroll
                for (int nf = 0; nf < 4; nf++) {
                    int zb = (nf >> 1) * 16 + (nf & 1) * 8 + tq * 2;
                    Z[row][zb]         = accH[mm][nf][0];
                    Z[row][zb + 1]     = accH[mm][nf][1];
                    Z[row + 8][zb]     = accH[mm][nf][2];
                    Z[row + 8][zb + 1] = accH[mm][nf][3];
                }
            }
        }
        __syncthreads();

        // ---- pointwise gates ----
        {
            float* ys_t = ys + (size_t)t * BB * HH;
            uint32_t* nh = (uint32_t*)g_hfrag[(t + 1) & 1];

            float h2[2], c2[2];
#pragma unroll
            for (int e = 0; e < 2; e++) {
                int zc = jj + e;
                float zi = Z[pb][zc]      + (e ? xi.y : xi.x);
                float zf = Z[pb][8 + zc]  + (e ? xf.y : xf.x);
                float zg = Z[pb][16 + zc] + (e ? xg.y : xg.x);
                float zo = Z[pb][24 + zc] + (e ? xo.y : xo.x);

                float ig = fast_sigmoid(zi);
                float fg = fast_sigmoid(zf);
                float gg = fast_tanh(zg);
                float og = fast_sigmoid(zo);

                float cc = fg * (e ? cv.y : cv.x) + ig * gg;
                c2[e] = cc;
                h2[e] = og * fast_tanh(cc);
            }

            *(float2*)&cT[(size_t)pb * HH + j0]   = *(float2*)c2;
            *(float2*)&ys_t[(size_t)pb * HH + j0] = *(float2*)h2;
            if (t == T_ - 1) *(float2*)&hT[(size_t)pb * HH + j0] = *(float2*)h2;

            __half2 hv = __floats2half2_rn(h2[0], h2[1]);
            nh[hoff] = *(uint32_t*)&hv;
        }

        grid_barrier();
    }
}

// ---------------------------------------------------------------------------
extern "C" void kernel_launch(void* const* d_in, const int* in_sizes, int n_in,
                              void* d_out, int out_size)
{
    const float* x  = (const float*)d_in[0];   // [T,B,D]
    const float* c0 = (const float*)d_in[1];   // [B,H]
    const float* h0 = (const float*)d_in[2];   // [B,H]
    const float* Wi = (const float*)d_in[3];   // [D,4H]
    const float* Wh = (const float*)d_in[4];   // [H,4H]
    const float* b  = (const float*)d_in[5];   // [4H]

    float* out = (float*)d_out;
    float* ys = out;                                  // [T,B,H]
    float* cT = out + (size_t)T_ * BB * HH;           // [B,H]
    float* hT = cT + (size_t)BB * HH;                 // [B,H]

    static int rec_smem_set = 0;
    if (!rec_smem_set) {
        cudaFuncSetAttribute(lstm_rec_mma,
                             cudaFuncAttributeMaxDynamicSharedMemorySize, REC_SMEM);
        rec_smem_set = 1;
    }

    prep_fused<<<16512, 256>>>(x, Wi, Wh, h0);               // launch 1
    gemm_wx_pack<<<10240, 256>>>(b);                         // launch 2
    lstm_rec_mma<<<RGRID, 256, REC_SMEM>>>(c0, ys, cT, hT);  // launch 3
}

// round 15
// speedup vs baseline: 2.1935x; 1.1055x over previous
#include <cuda_runtime.h>
#include <cuda_bf16.h>
#include <cuda_fp16.h>
#include <math.h>
#include <stdint.h>

#define T_   512
#define BB   64
#define HH   1024
#define N4   4096
#define RGRID 128   // blocks in persistent recurrence kernel
#define WLO_SCALE   2048.0f
#define WLO_INV     (1.0f / 2048.0f)

// ---------------- device scratch ----------------
__device__ float  g_zx[(size_t)T_ * BB * N4];        // x@Wi + b, fp32
__device__ __half g_xh[(size_t)T_ * BB * HH];        // x, single fp16
__device__ __half g_WiT_h[(size_t)N4 * HH];          // [n][k] fp16 hi
__device__ __half g_WiT_l[(size_t)N4 * HH];          // fp16 lo (unscaled, subnormal)
__device__ __half g_WhT_hi[(size_t)N4 * HH];         // [n][k] fp16 hi
__device__ __half g_WhT_lo[(size_t)N4 * HH];         // fp16 (w-hi)*2048

// Fragment-order operands for the recurrence MMA:
// A (h, single fp16): 4-deep ring [buf 4][m(4)][kc(64)][lane(32)] uint4
__device__ uint4 g_hfrag[4][4 * 64 * 32];
// B (Wh hi / lo_scaled): [bid(128)][nhalf(2)][kc(64)][lane(32)] uint4
__device__ uint4 g_whfrag_hi[(size_t)128 * 2 * 64 * 32];
__device__ uint4 g_whfrag_lo[(size_t)128 * 2 * 64 * 32];

// ---------------- dataflow sync state (zeroed per launch) -------------------
__device__ unsigned int g_readyq[(T_ + 1) * 4];   // per (step, quarter), target 32
__device__ unsigned int g_read_done[T_];          // per step, target 128

// ---------------- helpers ----------------
__device__ __forceinline__ float fast_sigmoid(float x)
{
    return __frcp_rn(1.f + __expf(-x));
}
__device__ __forceinline__ float fast_tanh(float x)
{
    return 1.f - 2.f * __frcp_rn(__expf(2.f * x) + 1.f);
}

__device__ __forceinline__ void spin_acquire_ge(const unsigned int* p, unsigned int tgt)
{
    unsigned int v;
    do {
        asm volatile("ld.acquire.gpu.global.u32 %0, [%1];" : "=r"(v) : "l"(p));
    } while (v < tgt);
}

// fp16 mma
__device__ __forceinline__ void mma16816h(float c[4],
                                          uint32_t a0, uint32_t a1, uint32_t a2, uint32_t a3,
                                          uint32_t b0, uint32_t b1)
{
    asm("mma.sync.aligned.m16n8k16.row.col.f32.f16.f16.f32 "
        "{%0,%1,%2,%3}, {%4,%5,%6,%7}, {%8,%9}, {%0,%1,%2,%3};"
        : "+f"(c[0]), "+f"(c[1]), "+f"(c[2]), "+f"(c[3])
        : "r"(a0), "r"(a1), "r"(a2), "r"(a3), "r"(b0), "r"(b1));
}

// ---------------------------------------------------------------------------
// Fused prep kernel (launch 1).
// ---------------------------------------------------------------------------
__global__ __launch_bounds__(256) void prep_fused(const float* __restrict__ x,
                                                  const float* __restrict__ Wi,
                                                  const float* __restrict__ Wh,
                                                  const float* __restrict__ h0)
{
    const int blk = blockIdx.x;
    const int tid = threadIdx.x;

    if (blk < 8192) {
        const float4* xv = (const float4*)x;
        __half2* dx = reinterpret_cast<__half2*>(g_xh);
#pragma unroll
        for (int j = 0; j < 4; j++) {
            int i = blk * 256 + tid + j * (8192 * 256);
            float4 v = xv[i];
            dx[2 * i]     = __floats2half2_rn(v.x, v.y);
            dx[2 * i + 1] = __floats2half2_rn(v.z, v.w);
        }
    } else if (blk < 16384) {
        __shared__ float tile[32][33];
        int which = (blk >= 12288);
        int tt = blk - (which ? 12288 : 8192);           // 0..4095
        const float* src = which ? Wh : Wi;
        int gx = (tt & 127) * 32;                        // n
        int gy = (tt >> 7) * 32;                         // k
#pragma unroll
        for (int i = 0; i < 4; i++) {
            int idx = tid + i * 256;
            int kl = idx >> 5, col = idx & 31;
            tile[kl][col] = src[(size_t)(gy + kl) * N4 + gx + col];
        }
        __syncthreads();
        if (which == 0) {
#pragma unroll
            for (int i = 0; i < 4; i++) {
                int idx = tid + i * 256;
                int nl = idx >> 5, kc = idx & 31;
                float v = tile[kc][nl];
                __half h = __float2half(v);
                __half l = __float2half(v - __half2float(h));   // subnormal ok
                g_WiT_h[(size_t)(gx + nl) * HH + gy + kc] = h;
                g_WiT_l[(size_t)(gx + nl) * HH + gy + kc] = l;
            }
        } else {
#pragma unroll
            for (int i = 0; i < 4; i++) {
                int idx = tid + i * 256;
                int nl = idx >> 5, kc = idx & 31;
                float v = tile[kc][nl];
                __half h = __float2half(v);
                __half l = __float2half((v - __half2float(h)) * WLO_SCALE);
                g_WhT_hi[(size_t)(gx + nl) * HH + gy + kc] = h;
                g_WhT_lo[(size_t)(gx + nl) * HH + gy + kc] = l;
            }
        }
    } else {
        int idx = (blk - 16384) * 256 + tid;             // 0 .. 64*512-1
        int b_ = idx >> 9;
        int p  = idx & 511;
        float v0 = h0[b_ * HH + 2 * p];
        float v1 = h0[b_ * HH + 2 * p + 1];
        __half2 hv = __floats2half2_rn(v0, v1);

        int kc = p >> 3, within = p & 7;
        int tq = within & 3, whi = within >> 2;
        int m = b_ >> 4, r16 = b_ & 15;
        int gq = r16 & 7, top = r16 >> 3;
        int lane = gq * 4 + tq;
        int w = whi * 2 + top;
        uint32_t off = (uint32_t)(((m * 64 + kc) * 32 + lane) * 4 + w);
        ((uint32_t*)g_hfrag[0])[off] = *(uint32_t*)&hv;
    }
}

// ---------------------------------------------------------------------------
// Launch 2 (fused): blocks [0,8192) = phase-1 GEMM tiles (fp16 2-pass);
// [8192,10240) = Wh fp16 fragment pack.
// ---------------------------------------------------------------------------
__global__ __launch_bounds__(256) void gemm_wx_pack(const float* __restrict__ bias)
{
    const int blk = blockIdx.x;
    const int tid = threadIdx.x;

    if (blk >= 8192) {
        int widx = (blk - 8192) * 256 + tid;             // 0 .. 524287
        int lane  = widx & 31;
        int kc    = (widx >> 5) & 63;
        int nhalf = (widx >> 11) & 1;
        int bidn  = widx >> 12;
        int gq = lane >> 2, tq = lane & 3;

        const uint32_t* WH = (const uint32_t*)g_WhT_hi;  // [col][512 pairs]
        const uint32_t* WL = (const uint32_t*)g_WhT_lo;
        uint32_t hi[4], lo[4];
#pragma unroll
        for (int w = 0; w < 4; w++) {
            int j = w >> 1, b = w & 1;
            int zc = nhalf * 16 + j * 8 + gq;
            int col = (zc >> 3) * 1024 + bidn * 8 + (zc & 7);
            int pair = kc * 8 + tq + b * 4;
            hi[w] = WH[(size_t)col * 512 + pair];
            lo[w] = WL[(size_t)col * 512 + pair];
        }
        g_whfrag_hi[widx] = make_uint4(hi[0], hi[1], hi[2], hi[3]);
        g_whfrag_lo[widx] = make_uint4(lo[0], lo[1], lo[2], lo[3]);
        return;
    }

    // ---- phase-1 GEMM: 128x128 tile, 8 warps, warp 64x32, kt=32, fp16 ----
    __shared__ uint32_t sA[128 * 20], sBh[128 * 20], sBl[128 * 20];

    const uint32_t* Xp = (const uint32_t*)g_xh;
    const uint32_t* Wh = (const uint32_t*)g_WiT_h;
    const uint32_t* Wl = (const uint32_t*)g_WiT_l;

    const int bn   = (blk & 31) * 128;
    const int bm   = (blk >> 5) * 128;
    const int lane = tid & 31, wp = tid >> 5;
    const int g    = lane >> 2, tq = lane & 3;
    const int wm   = (wp >> 2) * 64;
    const int wn   = (wp & 3) * 32;
    const int r0   = wp * 2 + (lane >> 4);
    const int kw   = lane & 15;

    float acc[4][4][4] = {};
    uint32_t pA[8], pBh[8], pBl[8];

    auto LOAD = [&](int kc) {
        int k0w = kc * 16;
#pragma unroll
        for (int i = 0; i < 8; i++) {
            int row = r0 + 16 * i;
            size_t ga = (size_t)(bm + row) * 512 + k0w + kw;
            size_t gb = (size_t)(bn + row) * 512 + k0w + kw;
            pA[i] = Xp[ga]; pBh[i] = Wh[gb]; pBl[i] = Wl[gb];
        }
    };
    auto STORE = [&]() {
#pragma unroll
        for (int i = 0; i < 8; i++) {
            int row = r0 + 16 * i;
            sA[row * 20 + kw]  = pA[i];
            sBh[row * 20 + kw] = pBh[i];
            sBl[row * 20 + kw] = pBl[i];
        }
    };

    LOAD(0); STORE(); __syncthreads();

    for (int kc = 0; kc < 32; kc++) {
        if (kc < 31) LOAD(kc + 1);
#pragma unroll
        for (int s = 0; s < 2; s++) {
            int kwb = s * 8;
            uint32_t bh[4][2], bl[4][2];
#pragma unroll
            for (int nf = 0; nf < 4; nf++) {
                int base = (wn + nf * 8 + g) * 20 + kwb + tq;
                bh[nf][0] = sBh[base]; bh[nf][1] = sBh[base + 4];
                bl[nf][0] = sBl[base]; bl[nf][1] = sBl[base + 4];
            }
#pragma unroll
            for (int mf = 0; mf < 4; mf++) {
                int rb = (wm + mf * 16 + g) * 20 + kwb + tq;
                uint32_t a0 = sA[rb], a1 = sA[rb + 160];
                uint32_t a2 = sA[rb + 4], a3 = sA[rb + 164];
#pragma unroll
                for (int nf = 0; nf < 4; nf++)
                    mma16816h(acc[mf][nf], a0, a1, a2, a3, bh[nf][0], bh[nf][1]);
#pragma unroll
                for (int nf = 0; nf < 4; nf++)
                    mma16816h(acc[mf][nf], a0, a1, a2, a3, bl[nf][0], bl[nf][1]);
            }
        }
        __syncthreads();
        if (kc < 31) { STORE(); __syncthreads(); }
    }

#pragma unroll
    for (int mf = 0; mf < 4; mf++) {
        int row0 = bm + wm + mf * 16 + g;
#pragma unroll
        for (int nf = 0; nf < 4; nf++) {
            int col = bn + wn + nf * 8 + tq * 2;
            float2 bb = *(const float2*)&bias[col];
            float2 v0, v1;
            v0.x = acc[mf][nf][0] + bb.x; v0.y = acc[mf][nf][1] + bb.y;
            v1.x = acc[mf][nf][2] + bb.x; v1.y = acc[mf][nf][3] + bb.y;
            *(float2*)&g_zx[(size_t)row0 * N4 + col]       = v0;
            *(float2*)&g_zx[(size_t)(row0 + 8) * N4 + col] = v1;
        }
    }
}

// ---------------------------------------------------------------------------
// Persistent recurrence (launch 3): 128 blocks x 256 thr.
// NO grid barrier: per-(step,quarter) ready counters gate each warp's k-loop;
// 4-deep h-frag ring + per-step read_done counters handle WAR across blocks.
// Wh fragments resident in smem; fp16 2-pass dual accumulators.
// ---------------------------------------------------------------------------
#define REC_SMEM    (131072 + 24576 + 8448)  // sB + Zpart + Z

__global__ __launch_bounds__(256, 1)
void lstm_rec_mma(const float* __restrict__ c0,
                  float* __restrict__ ys,
                  float* __restrict__ cT,
                  float* __restrict__ hT)
{
    extern __shared__ char dsm[];
    uint4* sB = (uint4*)dsm;                               // [hl(2)][nhalf(2)][kc64][lane32]
    float* Zpart = (float*)(dsm + 131072);                 // 6 * 1024
    float (*Z)[33] = (float(*)[33])(dsm + 131072 + 24576); // 64 x 33

    const int tid  = threadIdx.x, bid = blockIdx.x;
    const int lane = tid & 31, wp = tid >> 5;
    const int gq   = lane >> 2, tq = lane & 3;
    const int ks   = wp & 3;
    const int mp   = wp >> 2;
    const int jb   = bid * 8;
    const int myq  = bid >> 5;           // quarter this block produces

    // ---- load this block's Wh fragments into smem (once) ----
    {
        const uint4* GH = g_whfrag_hi + (size_t)bid * 4096;
        const uint4* GL = g_whfrag_lo + (size_t)bid * 4096;
#pragma unroll
        for (int i = 0; i < 16; i++) sB[tid + i * 256]        = GH[tid + i * 256];
#pragma unroll
        for (int i = 0; i < 16; i++) sB[4096 + tid + i * 256] = GL[tid + i * 256];
    }
    __syncthreads();

    // pointwise decode
    const int pb  = tid >> 2;
    const int jj  = (tid & 3) * 2;
    const int j0  = jb + jj;
    const int p_g   = j0 >> 1;
    const int kcw   = p_g >> 3, within = p_g & 7;
    const int ptq   = within & 3, pwhi = within >> 2;
    const int pm    = pb >> 4, r16 = pb & 15;
    const int pg    = r16 & 7, ptop = r16 >> 3;
    const uint32_t hoff = (uint32_t)((((pm * 64 + kcw) * 32) + pg * 4 + ptq) * 4
                                     + pwhi * 2 + ptop);

    for (int t = 0; t < T_; t++) {
        const uint4* AF = g_hfrag[t & 3];

        // ---- wait for this warp's input quarter (h cols produced at t-1) ----
        if (t > 0)
            spin_acquire_ge(&g_readyq[t * 4 + ks], 32u);

        // ---- prefetch pointwise operands ----
        const float* zx = g_zx + (size_t)t * BB * N4 + (size_t)pb * N4;
        const float* cp = (t == 0) ? c0 : cT;
        float2 xi = *(const float2*)&zx[j0];
        float2 xf = *(const float2*)&zx[HH + j0];
        float2 xg = *(const float2*)&zx[2 * HH + j0];
        float2 xo = *(const float2*)&zx[3 * HH + j0];
        float2 cv = *(const float2*)&cp[(size_t)pb * HH + j0];

        float accH[2][4][4], accL[2][4][4];
#pragma unroll
        for (int a = 0; a < 2; a++)
#pragma unroll
            for (int b = 0; b < 4; b++)
#pragma unroll
                for (int r = 0; r < 4; r++) { accH[a][b][r] = 0.f; accL[a][b][r] = 0.f; }

        // 4-slot pipeline for A (global); B read from smem per-iteration
        uint4 aF[4][2];
        const int kb = ks * 16;

        auto LOADA = [&](int i, int slot) {
            int off = (kb + i) * 32 + lane;
#pragma unroll
            for (int mm = 0; mm < 2; mm++)
                aF[slot][mm] = AF[(2 * mp + mm) * 2048 + off];
        };

        LOADA(0, 0); LOADA(1, 1); LOADA(2, 2);

#pragma unroll 4
        for (int i = 0; i < 16; i++) {
            int cur = i & 3;
            if (i + 3 < 16) LOADA(i + 3, (i + 3) & 3);

            int off = (kb + i) * 32 + lane;
            uint4 b0h = sB[off],        b1h = sB[2048 + off];
            uint4 b0l = sB[4096 + off], b1l = sB[6144 + off];
            uint4 a0 = aF[cur][0], a1 = aF[cur][1];

            // pass 1: h * W_hi  -> accH
            mma16816h(accH[0][0], a0.x, a0.y, a0.z, a0.w, b0h.x, b0h.y);
            mma16816h(accH[0][1], a0.x, a0.y, a0.z, a0.w, b0h.z, b0h.w);
            mma16816h(accH[0][2], a0.x, a0.y, a0.z, a0.w, b1h.x, b1h.y);
            mma16816h(accH[0][3], a0.x, a0.y, a0.z, a0.w, b1h.z, b1h.w);
            mma16816h(accH[1][0], a1.x, a1.y, a1.z, a1.w, b0h.x, b0h.y);
            mma16816h(accH[1][1], a1.x, a1.y, a1.z, a1.w, b0h.z, b0h.w);
            mma16816h(accH[1][2], a1.x, a1.y, a1.z, a1.w, b1h.x, b1h.y);
            mma16816h(accH[1][3], a1.x, a1.y, a1.z, a1.w, b1h.z, b1h.w);
            // pass 2: h * W_lo_scaled -> accL
            mma16816h(accL[0][0], a0.x, a0.y, a0.z, a0.w, b0l.x, b0l.y);
            mma16816h(accL[0][1], a0.x, a0.y, a0.z, a0.w, b0l.z, b0l.w);
            mma16816h(accL[0][2], a0.x, a0.y, a0.z, a0.w, b1l.x, b1l.y);
            mma16816h(accL[0][3], a0.x, a0.y, a0.z, a0.w, b1l.z, b1l.w);
            mma16816h(accL[1][0], a1.x, a1.y, a1.z, a1.w, b0l.x, b0l.y);
            mma16816h(accL[1][1], a1.x, a1.y, a1.z, a1.w, b0l.z, b0l.w);
            mma16816h(accL[1][2], a1.x, a1.y, a1.z, a1.w, b1l.x, b1l.y);
            mma16816h(accL[1][3], a1.x, a1.y, a1.z, a1.w, b1l.z, b1l.w);
        }

        // combine: z = accH + accL/2048
#pragma unroll
        for (int mm = 0; mm < 2; mm++)
#pragma unroll
            for (int nf = 0; nf < 4; nf++)
#pragma unroll
                for (int r = 0; r < 4; r++)
                    accH[mm][nf][r] = fmaf(accL[mm][nf][r], WLO_INV, accH[mm][nf][r]);

        // ---- one-stage K-split reduction: ks=1..3 -> smem, ks=0 sums ----
        if (ks != 0) {
            float* zp = Zpart + (mp * 3 + ks - 1) * 1024;
#pragma unroll
            for (int mm = 0; mm < 2; mm++)
#pragma unroll
                for (int nf = 0; nf < 4; nf++)
#pragma unroll
                    for (int r = 0; r < 4; r++)
                        zp[((mm * 4 + nf) * 4 + r) * 32 + lane] = accH[mm][nf][r];
        }
        __syncthreads();
        // all A-reads for step t consumed -> signal read_done
        if (tid == 255) atomicAdd(&g_read_done[t], 1u);
        if (ks == 0) {
#pragma unroll
            for (int s = 0; s < 3; s++) {
                const float* zp = Zpart + (mp * 3 + s) * 1024;
#pragma unroll
                for (int mm = 0; mm < 2; mm++)
#pragma unroll
                    for (int nf = 0; nf < 4; nf++)
#pragma unroll
                        for (int r = 0; r < 4; r++)
                            accH[mm][nf][r] += zp[((mm * 4 + nf) * 4 + r) * 32 + lane];
            }
#pragma unroll
            for (int mm = 0; mm < 2; mm++) {
                int row = mp * 32 + mm * 16 + gq;
#pragma unroll
                for (int nf = 0; nf < 4; nf++) {
                    int zb = (nf >> 1) * 16 + (nf & 1) * 8 + tq * 2;
                    Z[row][zb]         = accH[mm][nf][0];
                    Z[row][zb + 1]     = accH[mm][nf][1];
                    Z[row + 8][zb]     = accH[mm][nf][2];
                    Z[row + 8][zb + 1] = accH[mm][nf][3];
                }
            }
        }
        __syncthreads();

        // ---- WAR: before writing h-frag ring slot (t+1)&3 (last read at
        //      step t-3), ensure all blocks consumed step t-3 ----
        if (t >= 3) {
            if (tid == 0) spin_acquire_ge(&g_read_done[t - 3], 128u);
            __syncthreads();
        }

        // ---- pointwise gates ----
        {
            float* ys_t = ys + (size_t)t * BB * HH;
            uint32_t* nh = (uint32_t*)g_hfrag[(t + 1) & 3];

            float h2[2], c2[2];
#pragma unroll
            for (int e = 0; e < 2; e++) {
                int zc = jj + e;
                float zi = Z[pb][zc]      + (e ? xi.y : xi.x);
                float zf = Z[pb][8 + zc]  + (e ? xf.y : xf.x);
                float zg = Z[pb][16 + zc] + (e ? xg.y : xg.x);
                float zo = Z[pb][24 + zc] + (e ? xo.y : xo.x);

                float ig = fast_sigmoid(zi);
                float fg = fast_sigmoid(zf);
                float gg = fast_tanh(zg);
                float og = fast_sigmoid(zo);

                float cc = fg * (e ? cv.y : cv.x) + ig * gg;
                c2[e] = cc;
                h2[e] = og * fast_tanh(cc);
            }

            *(float2*)&cT[(size_t)pb * HH + j0]   = *(float2*)c2;
            *(float2*)&ys_t[(size_t)pb * HH + j0] = *(float2*)h2;
            if (t == T_ - 1) *(float2*)&hT[(size_t)pb * HH + j0] = *(float2*)h2;

            __half2 hv = __floats2half2_rn(h2[0], h2[1]);
            nh[hoff] = *(uint32_t*)&hv;
        }

        // ---- release: h cols for step t+1 are written ----
        __syncthreads();
        if (tid == 0 && t + 1 < T_) {
            __threadfence();
            atomicAdd(&g_readyq[(t + 1) * 4 + myq], 1u);
        }
    }
}

// ---------------------------------------------------------------------------
extern "C" void kernel_launch(void* const* d_in, const int* in_sizes, int n_in,
                              void* d_out, int out_size)
{
    const float* x  = (const float*)d_in[0];   // [T,B,D]
    const float* c0 = (const float*)d_in[1];   // [B,H]
    const float* h0 = (const float*)d_in[2];   // [B,H]
    const float* Wi = (const float*)d_in[3];   // [D,4H]
    const float* Wh = (const float*)d_in[4];   // [H,4H]
    const float* b  = (const float*)d_in[5];   // [4H]

    float* out = (float*)d_out;
    float* ys = out;                                  // [T,B,H]
    float* cT = out + (size_t)T_ * BB * HH;           // [B,H]
    float* hT = cT + (size_t)BB * HH;                 // [B,H]

    static unsigned int* d_rq = nullptr;
    static unsigned int* d_rd = nullptr;
    static int rec_smem_set = 0;
    if (!rec_smem_set) {
        cudaFuncSetAttribute(lstm_rec_mma,
                             cudaFuncAttributeMaxDynamicSharedMemorySize, REC_SMEM);
        cudaGetSymbolAddress((void**)&d_rq, g_readyq);
        cudaGetSymbolAddress((void**)&d_rd, g_read_done);
        rec_smem_set = 1;
    }

    // zero dataflow counters (graph-legal async memset nodes)
    cudaMemsetAsync(d_rq, 0, sizeof(unsigned int) * (T_ + 1) * 4);
    cudaMemsetAsync(d_rd, 0, sizeof(unsigned int) * T_);

    prep_fused<<<16512, 256>>>(x, Wi, Wh, h0);               // launch 1
    gemm_wx_pack<<<10240, 256>>>(b);                         // launch 2
    lstm_rec_mma<<<RGRID, 256, REC_SMEM>>>(c0, ys, cT, hT);  // launch 3
}

// round 16
// speedup vs baseline: 2.2956x; 1.0466x over previous
#include <cuda_runtime.h>
#include <cuda_bf16.h>
#include <cuda_fp16.h>
#include <math.h>
#include <stdint.h>

#define T_   512
#define BB   64
#define HH   1024
#define N4   4096
#define RGRID 128   // blocks in persistent recurrence kernel
#define WLO_SCALE   2048.0f
#define WLO_INV     (1.0f / 2048.0f)

// ---------------- device scratch ----------------
__device__ float  g_zx[(size_t)T_ * BB * N4];        // x@Wi + b, fp32
__device__ __half g_xh[(size_t)T_ * BB * HH];        // x, single fp16
__device__ __half g_WiT_h[(size_t)N4 * HH];          // [n][k] fp16 hi
__device__ __half g_WiT_l[(size_t)N4 * HH];          // fp16 lo (unscaled, subnormal)
__device__ __half g_WhT_hi[(size_t)N4 * HH];         // [n][k] fp16 hi
__device__ __half g_WhT_lo[(size_t)N4 * HH];         // fp16 (w-hi)*2048

// Fragment-order operands for the recurrence MMA:
// A (h, single fp16): 4-deep ring [buf 4][m(4)][kc(64)][lane(32)] uint4
__device__ uint4 g_hfrag[4][4 * 64 * 32];
// B (Wh hi / lo_scaled): [bid(128)][nhalf(2)][kc(64)][lane(32)] uint4
__device__ uint4 g_whfrag_hi[(size_t)128 * 2 * 64 * 32];
__device__ uint4 g_whfrag_lo[(size_t)128 * 2 * 64 * 32];

// ---------------- dataflow sync state (zeroed per launch) -------------------
__device__ unsigned int g_readyq[(T_ + 1) * 4];   // per (step, quarter), target 32
__device__ unsigned int g_read_done[T_];          // per step, target 128

// ---------------- helpers ----------------
__device__ __forceinline__ float fast_sigmoid(float x)
{
    return __frcp_rn(1.f + __expf(-x));
}
__device__ __forceinline__ float fast_tanh(float x)
{
    return 1.f - 2.f * __frcp_rn(__expf(2.f * x) + 1.f);
}

__device__ __forceinline__ void spin_acquire_ge(const unsigned int* p, unsigned int tgt)
{
    unsigned int v;
    do {
        asm volatile("ld.acquire.gpu.global.u32 %0, [%1];" : "=r"(v) : "l"(p));
    } while (v < tgt);
}

// fp16 mma
__device__ __forceinline__ void mma16816h(float c[4],
                                          uint32_t a0, uint32_t a1, uint32_t a2, uint32_t a3,
                                          uint32_t b0, uint32_t b1)
{
    asm("mma.sync.aligned.m16n8k16.row.col.f32.f16.f16.f32 "
        "{%0,%1,%2,%3}, {%4,%5,%6,%7}, {%8,%9}, {%0,%1,%2,%3};"
        : "+f"(c[0]), "+f"(c[1]), "+f"(c[2]), "+f"(c[3])
        : "r"(a0), "r"(a1), "r"(a2), "r"(a3), "r"(b0), "r"(b1));
}

// ---------------------------------------------------------------------------
// Fused prep kernel (launch 1).
// ---------------------------------------------------------------------------
__global__ __launch_bounds__(256) void prep_fused(const float* __restrict__ x,
                                                  const float* __restrict__ Wi,
                                                  const float* __restrict__ Wh,
                                                  const float* __restrict__ h0)
{
    const int blk = blockIdx.x;
    const int tid = threadIdx.x;

    if (blk < 8192) {
        const float4* xv = (const float4*)x;
        __half2* dx = reinterpret_cast<__half2*>(g_xh);
#pragma unroll
        for (int j = 0; j < 4; j++) {
            int i = blk * 256 + tid + j * (8192 * 256);
            float4 v = xv[i];
            dx[2 * i]     = __floats2half2_rn(v.x, v.y);
            dx[2 * i + 1] = __floats2half2_rn(v.z, v.w);
        }
    } else if (blk < 16384) {
        __shared__ float tile[32][33];
        int which = (blk >= 12288);
        int tt = blk - (which ? 12288 : 8192);           // 0..4095
        const float* src = which ? Wh : Wi;
        int gx = (tt & 127) * 32;                        // n
        int gy = (tt >> 7) * 32;                         // k
#pragma unroll
        for (int i = 0; i < 4; i++) {
            int idx = tid + i * 256;
            int kl = idx >> 5, col = idx & 31;
            tile[kl][col] = src[(size_t)(gy + kl) * N4 + gx + col];
        }
        __syncthreads();
        if (which == 0) {
#pragma unroll
            for (int i = 0; i < 4; i++) {
                int idx = tid + i * 256;
                int nl = idx >> 5, kc = idx & 31;
                float v = tile[kc][nl];
                __half h = __float2half(v);
                __half l = __float2half(v - __half2float(h));   // subnormal ok
                g_WiT_h[(size_t)(gx + nl) * HH + gy + kc] = h;
                g_WiT_l[(size_t)(gx + nl) * HH + gy + kc] = l;
            }
        } else {
#pragma unroll
            for (int i = 0; i < 4; i++) {
                int idx = tid + i * 256;
                int nl = idx >> 5, kc = idx & 31;
                float v = tile[kc][nl];
                __half h = __float2half(v);
                __half l = __float2half((v - __half2float(h)) * WLO_SCALE);
                g_WhT_hi[(size_t)(gx + nl) * HH + gy + kc] = h;
                g_WhT_lo[(size_t)(gx + nl) * HH + gy + kc] = l;
            }
        }
    } else {
        int idx = (blk - 16384) * 256 + tid;             // 0 .. 64*512-1
        int b_ = idx >> 9;
        int p  = idx & 511;
        float v0 = h0[b_ * HH + 2 * p];
        float v1 = h0[b_ * HH + 2 * p + 1];
        __half2 hv = __floats2half2_rn(v0, v1);

        int kc = p >> 3, within = p & 7;
        int tq = within & 3, whi = within >> 2;
        int m = b_ >> 4, r16 = b_ & 15;
        int gq = r16 & 7, top = r16 >> 3;
        int lane = gq * 4 + tq;
        int w = whi * 2 + top;
        uint32_t off = (uint32_t)(((m * 64 + kc) * 32 + lane) * 4 + w);
        ((uint32_t*)g_hfrag[0])[off] = *(uint32_t*)&hv;
    }
}

// ---------------------------------------------------------------------------
// Launch 2 (fused): blocks [0,8192) = phase-1 GEMM tiles (fp16 2-pass);
// [8192,10240) = Wh fp16 fragment pack.
// ---------------------------------------------------------------------------
__global__ __launch_bounds__(256) void gemm_wx_pack(const float* __restrict__ bias)
{
    const int blk = blockIdx.x;
    const int tid = threadIdx.x;

    if (blk >= 8192) {
        int widx = (blk - 8192) * 256 + tid;             // 0 .. 524287
        int lane  = widx & 31;
        int kc    = (widx >> 5) & 63;
        int nhalf = (widx >> 11) & 1;
        int bidn  = widx >> 12;
        int gq = lane >> 2, tq = lane & 3;

        const uint32_t* WH = (const uint32_t*)g_WhT_hi;  // [col][512 pairs]
        const uint32_t* WL = (const uint32_t*)g_WhT_lo;
        uint32_t hi[4], lo[4];
#pragma unroll
        for (int w = 0; w < 4; w++) {
            int j = w >> 1, b = w & 1;
            int zc = nhalf * 16 + j * 8 + gq;
            int col = (zc >> 3) * 1024 + bidn * 8 + (zc & 7);
            int pair = kc * 8 + tq + b * 4;
            hi[w] = WH[(size_t)col * 512 + pair];
            lo[w] = WL[(size_t)col * 512 + pair];
        }
        g_whfrag_hi[widx] = make_uint4(hi[0], hi[1], hi[2], hi[3]);
        g_whfrag_lo[widx] = make_uint4(lo[0], lo[1], lo[2], lo[3]);
        return;
    }

    // ---- phase-1 GEMM: 128x128 tile, 8 warps, warp 64x32, kt=32, fp16 ----
    __shared__ uint32_t sA[128 * 20], sBh[128 * 20], sBl[128 * 20];

    const uint32_t* Xp = (const uint32_t*)g_xh;
    const uint32_t* Wh = (const uint32_t*)g_WiT_h;
    const uint32_t* Wl = (const uint32_t*)g_WiT_l;

    const int bn   = (blk & 31) * 128;
    const int bm   = (blk >> 5) * 128;
    const int lane = tid & 31, wp = tid >> 5;
    const int g    = lane >> 2, tq = lane & 3;
    const int wm   = (wp >> 2) * 64;
    const int wn   = (wp & 3) * 32;
    const int r0   = wp * 2 + (lane >> 4);
    const int kw   = lane & 15;

    float acc[4][4][4] = {};
    uint32_t pA[8], pBh[8], pBl[8];

    auto LOAD = [&](int kc) {
        int k0w = kc * 16;
#pragma unroll
        for (int i = 0; i < 8; i++) {
            int row = r0 + 16 * i;
            size_t ga = (size_t)(bm + row) * 512 + k0w + kw;
            size_t gb = (size_t)(bn + row) * 512 + k0w + kw;
            pA[i] = Xp[ga]; pBh[i] = Wh[gb]; pBl[i] = Wl[gb];
        }
    };
    auto STORE = [&]() {
#pragma unroll
        for (int i = 0; i < 8; i++) {
            int row = r0 + 16 * i;
            sA[row * 20 + kw]  = pA[i];
            sBh[row * 20 + kw] = pBh[i];
            sBl[row * 20 + kw] = pBl[i];
        }
    };

    LOAD(0); STORE(); __syncthreads();

    for (int kc = 0; kc < 32; kc++) {
        if (kc < 31) LOAD(kc + 1);
#pragma unroll
        for (int s = 0; s < 2; s++) {
            int kwb = s * 8;
            uint32_t bh[4][2], bl[4][2];
#pragma unroll
            for (int nf = 0; nf < 4; nf++) {
                int base = (wn + nf * 8 + g) * 20 + kwb + tq;
                bh[nf][0] = sBh[base]; bh[nf][1] = sBh[base + 4];
                bl[nf][0] = sBl[base]; bl[nf][1] = sBl[base + 4];
            }
#pragma unroll
            for (int mf = 0; mf < 4; mf++) {
                int rb = (wm + mf * 16 + g) * 20 + kwb + tq;
                uint32_t a0 = sA[rb], a1 = sA[rb + 160];
                uint32_t a2 = sA[rb + 4], a3 = sA[rb + 164];
#pragma unroll
                for (int nf = 0; nf < 4; nf++)
                    mma16816h(acc[mf][nf], a0, a1, a2, a3, bh[nf][0], bh[nf][1]);
#pragma unroll
                for (int nf = 0; nf < 4; nf++)
                    mma16816h(acc[mf][nf], a0, a1, a2, a3, bl[nf][0], bl[nf][1]);
            }
        }
        __syncthreads();
        if (kc < 31) { STORE(); __syncthreads(); }
    }

#pragma unroll
    for (int mf = 0; mf < 4; mf++) {
        int row0 = bm + wm + mf * 16 + g;
#pragma unroll
        for (int nf = 0; nf < 4; nf++) {
            int col = bn + wn + nf * 8 + tq * 2;
            float2 bb = *(const float2*)&bias[col];
            float2 v0, v1;
            v0.x = acc[mf][nf][0] + bb.x; v0.y = acc[mf][nf][1] + bb.y;
            v1.x = acc[mf][nf][2] + bb.x; v1.y = acc[mf][nf][3] + bb.y;
            *(float2*)&g_zx[(size_t)row0 * N4 + col]       = v0;
            *(float2*)&g_zx[(size_t)(row0 + 8) * N4 + col] = v1;
        }
    }
}

// ---------------------------------------------------------------------------
// Persistent recurrence (launch 3): 128 blocks x 256 thr.
// Dataflow sync (no grid barrier). Flattened reduction: all warps store
// K-split partials to P[ks][64][33]; pointwise sums 4 partials directly
// (ascending ks -> bitwise-identical to previous chain). 2 syncthreads/step.
// ---------------------------------------------------------------------------
#define P_STRIDE    2112                   // 64*33 floats per ks slice
#define REC_SMEM    (131072 + 4 * P_STRIDE * 4)   // sB (128K) + P (33.8K)

__global__ __launch_bounds__(256, 1)
void lstm_rec_mma(const float* __restrict__ c0,
                  float* __restrict__ ys,
                  float* __restrict__ cT,
                  float* __restrict__ hT)
{
    extern __shared__ char dsm[];
    uint4* sB = (uint4*)dsm;                 // [hl(2)][nhalf(2)][kc64][lane32]
    float* P  = (float*)(dsm + 131072);      // [ks(4)][row(64)][col(33)]

    const int tid  = threadIdx.x, bid = blockIdx.x;
    const int lane = tid & 31, wp = tid >> 5;
    const int gq   = lane >> 2, tq = lane & 3;
    const int ks   = wp & 3;
    const int mp   = wp >> 2;
    const int jb   = bid * 8;
    const int myq  = bid >> 5;           // quarter this block produces

    // ---- load this block's Wh fragments into smem (once) ----
    {
        const uint4* GH = g_whfrag_hi + (size_t)bid * 4096;
        const uint4* GL = g_whfrag_lo + (size_t)bid * 4096;
#pragma unroll
        for (int i = 0; i < 16; i++) sB[tid + i * 256]        = GH[tid + i * 256];
#pragma unroll
        for (int i = 0; i < 16; i++) sB[4096 + tid + i * 256] = GL[tid + i * 256];
    }
    __syncthreads();

    // pointwise decode
    const int pb  = tid >> 2;
    const int jj  = (tid & 3) * 2;
    const int j0  = jb + jj;
    const int p_g   = j0 >> 1;
    const int kcw   = p_g >> 3, within = p_g & 7;
    const int ptq   = within & 3, pwhi = within >> 2;
    const int pm    = pb >> 4, r16 = pb & 15;
    const int pg    = r16 & 7, ptop = r16 >> 3;
    const uint32_t hoff = (uint32_t)((((pm * 64 + kcw) * 32) + pg * 4 + ptq) * 4
                                     + pwhi * 2 + ptop);

    for (int t = 0; t < T_; t++) {
        const uint4* AF = g_hfrag[t & 3];

        // ---- prefetch pointwise operands BEFORE the spin (t-only deps) ----
        const float* zx = g_zx + (size_t)t * BB * N4 + (size_t)pb * N4;
        const float* cp = (t == 0) ? c0 : cT;
        float2 xi = *(const float2*)&zx[j0];
        float2 xf = *(const float2*)&zx[HH + j0];
        float2 xg = *(const float2*)&zx[2 * HH + j0];
        float2 xo = *(const float2*)&zx[3 * HH + j0];
        float2 cv = *(const float2*)&cp[(size_t)pb * HH + j0];

        // ---- wait for this warp's input quarter (h cols produced at t-1) ----
        if (t > 0)
            spin_acquire_ge(&g_readyq[t * 4 + ks], 32u);

        float accH[2][4][4], accL[2][4][4];
#pragma unroll
        for (int a = 0; a < 2; a++)
#pragma unroll
            for (int b = 0; b < 4; b++)
#pragma unroll
                for (int r = 0; r < 4; r++) { accH[a][b][r] = 0.f; accL[a][b][r] = 0.f; }

        // 4-slot pipeline for A (global); B read from smem per-iteration
        uint4 aF[4][2];
        const int kb = ks * 16;

        auto LOADA = [&](int i, int slot) {
            int off = (kb + i) * 32 + lane;
#pragma unroll
            for (int mm = 0; mm < 2; mm++)
                aF[slot][mm] = AF[(2 * mp + mm) * 2048 + off];
        };

        LOADA(0, 0); LOADA(1, 1); LOADA(2, 2);

#pragma unroll 4
        for (int i = 0; i < 16; i++) {
            int cur = i & 3;
            if (i + 3 < 16) LOADA(i + 3, (i + 3) & 3);

            int off = (kb + i) * 32 + lane;
            uint4 b0h = sB[off],        b1h = sB[2048 + off];
            uint4 b0l = sB[4096 + off], b1l = sB[6144 + off];
            uint4 a0 = aF[cur][0], a1 = aF[cur][1];

            // pass 1: h * W_hi  -> accH
            mma16816h(accH[0][0], a0.x, a0.y, a0.z, a0.w, b0h.x, b0h.y);
            mma16816h(accH[0][1], a0.x, a0.y, a0.z, a0.w, b0h.z, b0h.w);
            mma16816h(accH[0][2], a0.x, a0.y, a0.z, a0.w, b1h.x, b1h.y);
            mma16816h(accH[0][3], a0.x, a0.y, a0.z, a0.w, b1h.z, b1h.w);
            mma16816h(accH[1][0], a1.x, a1.y, a1.z, a1.w, b0h.x, b0h.y);
            mma16816h(accH[1][1], a1.x, a1.y, a1.z, a1.w, b0h.z, b0h.w);
            mma16816h(accH[1][2], a1.x, a1.y, a1.z, a1.w, b1h.x, b1h.y);
            mma16816h(accH[1][3], a1.x, a1.y, a1.z, a1.w, b1h.z, b1h.w);
            // pass 2: h * W_lo_scaled -> accL
            mma16816h(accL[0][0], a0.x, a0.y, a0.z, a0.w, b0l.x, b0l.y);
            mma16816h(accL[0][1], a0.x, a0.y, a0.z, a0.w, b0l.z, b0l.w);
            mma16816h(accL[0][2], a0.x, a0.y, a0.z, a0.w, b1l.x, b1l.y);
            mma16816h(accL[0][3], a0.x, a0.y, a0.z, a0.w, b1l.z, b1l.w);
            mma16816h(accL[1][0], a1.x, a1.y, a1.z, a1.w, b0l.x, b0l.y);
            mma16816h(accL[1][1], a1.x, a1.y, a1.z, a1.w, b0l.z, b0l.w);
            mma16816h(accL[1][2], a1.x, a1.y, a1.z, a1.w, b1l.x, b1l.y);
            mma16816h(accL[1][3], a1.x, a1.y, a1.z, a1.w, b1l.z, b1l.w);
        }

        // combine: z_part = accH + accL/2048; store ALL partials to P
        {
            float* Pk = P + ks * P_STRIDE;
#pragma unroll
            for (int mm = 0; mm < 2; mm++) {
                int row = mp * 32 + mm * 16 + gq;
#pragma unroll
                for (int nf = 0; nf < 4; nf++) {
                    int zb = (nf >> 1) * 16 + (nf & 1) * 8 + tq * 2;
                    float v0 = fmaf(accL[mm][nf][0], WLO_INV, accH[mm][nf][0]);
                    float v1 = fmaf(accL[mm][nf][1], WLO_INV, accH[mm][nf][1]);
                    float v2 = fmaf(accL[mm][nf][2], WLO_INV, accH[mm][nf][2]);
                    float v3 = fmaf(accL[mm][nf][3], WLO_INV, accH[mm][nf][3]);
                    Pk[row * 33 + zb]           = v0;
                    Pk[row * 33 + zb + 1]       = v1;
                    Pk[(row + 8) * 33 + zb]     = v2;
                    Pk[(row + 8) * 33 + zb + 1] = v3;
                }
            }
        }

        // A-reads for step t done -> signal; WAR wait for ring slot reuse
        if (tid == 255) atomicAdd(&g_read_done[t], 1u);
        if (t >= 3 && tid == 0) spin_acquire_ge(&g_read_done[t - 3], 128u);
        __syncthreads();

        // ---- pointwise gates: sum 4 ks-partials directly (ascending ks) ----
        {
            float* ys_t = ys + (size_t)t * BB * HH;
            uint32_t* nh = (uint32_t*)g_hfrag[(t + 1) & 3];
            const float* Pr = P + pb * 33;

            float h2[2], c2[2];
#pragma unroll
            for (int e = 0; e < 2; e++) {
                int zc = jj + e;
                float zi = Pr[zc],      zf = Pr[8 + zc];
                float zg = Pr[16 + zc], zo = Pr[24 + zc];
#pragma unroll
                for (int s = 1; s < 4; s++) {
                    const float* Ps = Pr + s * P_STRIDE;
                    zi += Ps[zc];      zf += Ps[8 + zc];
                    zg += Ps[16 + zc]; zo += Ps[24 + zc];
                }
                zi += (e ? xi.y : xi.x);
                zf += (e ? xf.y : xf.x);
                zg += (e ? xg.y : xg.x);
                zo += (e ? xo.y : xo.x);

                float ig = fast_sigmoid(zi);
                float fg = fast_sigmoid(zf);
                float gg = fast_tanh(zg);
                float og = fast_sigmoid(zo);

                float cc = fg * (e ? cv.y : cv.x) + ig * gg;
                c2[e] = cc;
                h2[e] = og * fast_tanh(cc);
            }

            *(float2*)&cT[(size_t)pb * HH + j0]   = *(float2*)c2;
            *(float2*)&ys_t[(size_t)pb * HH + j0] = *(float2*)h2;
            if (t == T_ - 1) *(float2*)&hT[(size_t)pb * HH + j0] = *(float2*)h2;

            __half2 hv = __floats2half2_rn(h2[0], h2[1]);
            nh[hoff] = *(uint32_t*)&hv;
        }

        // ---- release: h cols for step t+1 are written ----
        __syncthreads();
        if (tid == 0 && t + 1 < T_) {
            __threadfence();
            atomicAdd(&g_readyq[(t + 1) * 4 + myq], 1u);
        }
    }
}

// ---------------------------------------------------------------------------
extern "C" void kernel_launch(void* const* d_in, const int* in_sizes, int n_in,
                              void* d_out, int out_size)
{
    const float* x  = (const float*)d_in[0];   // [T,B,D]
    const float* c0 = (const float*)d_in[1];   // [B,H]
    const float* h0 = (const float*)d_in[2];   // [B,H]
    const float* Wi = (const float*)d_in[3];   // [D,4H]
    const float* Wh = (const float*)d_in[4];   // [H,4H]
    const float* b  = (const float*)d_in[5];   // [4H]

    float* out = (float*)d_out;
    float* ys = out;                                  // [T,B,H]
    float* cT = out + (size_t)T_ * BB * HH;           // [B,H]
    float* hT = cT + (size_t)BB * HH;                 // [B,H]

    static unsigned int* d_rq = nullptr;
    static unsigned int* d_rd = nullptr;
    static int rec_smem_set = 0;
    if (!rec_smem_set) {
        cudaFuncSetAttribute(lstm_rec_mma,
                             cudaFuncAttributeMaxDynamicSharedMemorySize, REC_SMEM);
        cudaGetSymbolAddress((void**)&d_rq, g_readyq);
        cudaGetSymbolAddress((void**)&d_rd, g_read_done);
        rec_smem_set = 1;
    }

    // zero dataflow counters (graph-legal async memset nodes)
    cudaMemsetAsync(d_rq, 0, sizeof(unsigned int) * (T_ + 1) * 4);
    cudaMemsetAsync(d_rd, 0, sizeof(unsigned int) * T_);

    prep_fused<<<16512, 256>>>(x, Wi, Wh, h0);               // launch 1
    gemm_wx_pack<<<10240, 256>>>(b);                         // launch 2
    lstm_rec_mma<<<RGRID, 256, REC_SMEM>>>(c0, ys, cT, hT);  // launch 3
}

// round 17
// speedup vs baseline: 2.3061x; 1.0045x over previous
#include <cuda_runtime.h>
#include <cuda_bf16.h>
#include <cuda_fp16.h>
#include <math.h>
#include <stdint.h>

#define T_   512
#define BB   64
#define HH   1024
#define N4   4096
#define RGRID 128   // blocks in persistent recurrence kernel
#define WLO_SCALE   2048.0f
#define WLO_INV     (1.0f / 2048.0f)

// ---------------- device scratch ----------------
__device__ float  g_zx[(size_t)T_ * BB * N4];        // x@Wi + b, fp32
__device__ __half g_xh[(size_t)T_ * BB * HH];        // x, single fp16
__device__ __half g_WiT_h[(size_t)N4 * HH];          // [n][k] fp16 hi
__device__ __half g_WiT_l[(size_t)N4 * HH];          // fp16 lo (unscaled, subnormal)
__device__ __half g_WhT_hi[(size_t)N4 * HH];         // [n][k] fp16 hi
__device__ __half g_WhT_lo[(size_t)N4 * HH];         // fp16 (w-hi)*2048

// Fragment-order operands for the recurrence MMA:
// A (h, single fp16): 4-deep ring [buf 4][m(4)][kc(64)][lane(32)] uint4
__device__ uint4 g_hfrag[4][4 * 64 * 32];
// B (Wh hi / lo_scaled): [bid(128)][nhalf(2)][kc(64)][lane(32)] uint4
__device__ uint4 g_whfrag_hi[(size_t)128 * 2 * 64 * 32];
__device__ uint4 g_whfrag_lo[(size_t)128 * 2 * 64 * 32];

// ---------------- dataflow sync state (zeroed per launch) -------------------
__device__ unsigned int g_readyq[(T_ + 1) * 4];   // per (step, quarter), target 32
__device__ unsigned int g_read_done[T_];          // per step, target 128

// ---------------- helpers ----------------
__device__ __forceinline__ float fast_sigmoid(float x)
{
    return __frcp_rn(1.f + __expf(-x));
}
__device__ __forceinline__ float fast_tanh(float x)
{
    return 1.f - 2.f * __frcp_rn(__expf(2.f * x) + 1.f);
}

// single-thread spin with backoff (call from one lane/thread only)
__device__ __forceinline__ void spin1_acquire_ge(const unsigned int* p, unsigned int tgt)
{
    unsigned int v;
    int it = 0;
    for (;;) {
        asm volatile("ld.acquire.gpu.global.u32 %0, [%1];" : "=r"(v) : "l"(p));
        if (v >= tgt) break;
        if (++it > 4) __nanosleep(64);
    }
}

// warp-collective: lane 0 polls, others wait at syncwarp
__device__ __forceinline__ void spin_warp_acquire_ge(const unsigned int* p, unsigned int tgt)
{
    if ((threadIdx.x & 31) == 0) spin1_acquire_ge(p, tgt);
    __syncwarp();
}

// fp16 mma
__device__ __forceinline__ void mma16816h(float c[4],
                                          uint32_t a0, uint32_t a1, uint32_t a2, uint32_t a3,
                                          uint32_t b0, uint32_t b1)
{
    asm("mma.sync.aligned.m16n8k16.row.col.f32.f16.f16.f32 "
        "{%0,%1,%2,%3}, {%4,%5,%6,%7}, {%8,%9}, {%0,%1,%2,%3};"
        : "+f"(c[0]), "+f"(c[1]), "+f"(c[2]), "+f"(c[3])
        : "r"(a0), "r"(a1), "r"(a2), "r"(a3), "r"(b0), "r"(b1));
}

// ---------------------------------------------------------------------------
// Fused prep kernel (launch 1).
// ---------------------------------------------------------------------------
__global__ __launch_bounds__(256) void prep_fused(const float* __restrict__ x,
                                                  const float* __restrict__ Wi,
                                                  const float* __restrict__ Wh,
                                                  const float* __restrict__ h0)
{
    const int blk = blockIdx.x;
    const int tid = threadIdx.x;

    if (blk < 8192) {
        const float4* xv = (const float4*)x;
        __half2* dx = reinterpret_cast<__half2*>(g_xh);
#pragma unroll
        for (int j = 0; j < 4; j++) {
            int i = blk * 256 + tid + j * (8192 * 256);
            float4 v = xv[i];
            dx[2 * i]     = __floats2half2_rn(v.x, v.y);
            dx[2 * i + 1] = __floats2half2_rn(v.z, v.w);
        }
    } else if (blk < 16384) {
        __shared__ float tile[32][33];
        int which = (blk >= 12288);
        int tt = blk - (which ? 12288 : 8192);           // 0..4095
        const float* src = which ? Wh : Wi;
        int gx = (tt & 127) * 32;                        // n
        int gy = (tt >> 7) * 32;                         // k
#pragma unroll
        for (int i = 0; i < 4; i++) {
            int idx = tid + i * 256;
            int kl = idx >> 5, col = idx & 31;
            tile[kl][col] = src[(size_t)(gy + kl) * N4 + gx + col];
        }
        __syncthreads();
        if (which == 0) {
#pragma unroll
            for (int i = 0; i < 4; i++) {
                int idx = tid + i * 256;
                int nl = idx >> 5, kc = idx & 31;
                float v = tile[kc][nl];
                __half h = __float2half(v);
                __half l = __float2half(v - __half2float(h));   // subnormal ok
                g_WiT_h[(size_t)(gx + nl) * HH + gy + kc] = h;
                g_WiT_l[(size_t)(gx + nl) * HH + gy + kc] = l;
            }
        } else {
#pragma unroll
            for (int i = 0; i < 4; i++) {
                int idx = tid + i * 256;
                int nl = idx >> 5, kc = idx & 31;
                float v = tile[kc][nl];
                __half h = __float2half(v);
                __half l = __float2half((v - __half2float(h)) * WLO_SCALE);
                g_WhT_hi[(size_t)(gx + nl) * HH + gy + kc] = h;
                g_WhT_lo[(size_t)(gx + nl) * HH + gy + kc] = l;
            }
        }
    } else {
        int idx = (blk - 16384) * 256 + tid;             // 0 .. 64*512-1
        int b_ = idx >> 9;
        int p  = idx & 511;
        float v0 = h0[b_ * HH + 2 * p];
        float v1 = h0[b_ * HH + 2 * p + 1];
        __half2 hv = __floats2half2_rn(v0, v1);

        int kc = p >> 3, within = p & 7;
        int tq = within & 3, whi = within >> 2;
        int m = b_ >> 4, r16 = b_ & 15;
        int gq = r16 & 7, top = r16 >> 3;
        int lane = gq * 4 + tq;
        int w = whi * 2 + top;
        uint32_t off = (uint32_t)(((m * 64 + kc) * 32 + lane) * 4 + w);
        ((uint32_t*)g_hfrag[0])[off] = *(uint32_t*)&hv;
    }
}

// ---------------------------------------------------------------------------
// Launch 2 (fused): blocks [0,8192) = phase-1 GEMM tiles (fp16 2-pass);
// [8192,10240) = Wh fp16 fragment pack.
// ---------------------------------------------------------------------------
__global__ __launch_bounds__(256) void gemm_wx_pack(const float* __restrict__ bias)
{
    const int blk = blockIdx.x;
    const int tid = threadIdx.x;

    if (blk >= 8192) {
        int widx = (blk - 8192) * 256 + tid;             // 0 .. 524287
        int lane  = widx & 31;
        int kc    = (widx >> 5) & 63;
        int nhalf = (widx >> 11) & 1;
        int bidn  = widx >> 12;
        int gq = lane >> 2, tq = lane & 3;

        const uint32_t* WH = (const uint32_t*)g_WhT_hi;  // [col][512 pairs]
        const uint32_t* WL = (const uint32_t*)g_WhT_lo;
        uint32_t hi[4], lo[4];
#pragma unroll
        for (int w = 0; w < 4; w++) {
            int j = w >> 1, b = w & 1;
            int zc = nhalf * 16 + j * 8 + gq;
            int col = (zc >> 3) * 1024 + bidn * 8 + (zc & 7);
            int pair = kc * 8 + tq + b * 4;
            hi[w] = WH[(size_t)col * 512 + pair];
            lo[w] = WL[(size_t)col * 512 + pair];
        }
        g_whfrag_hi[widx] = make_uint4(hi[0], hi[1], hi[2], hi[3]);
        g_whfrag_lo[widx] = make_uint4(lo[0], lo[1], lo[2], lo[3]);
        return;
    }

    // ---- phase-1 GEMM: 128x128 tile, 8 warps, warp 64x32, kt=32, fp16 ----
    __shared__ uint32_t sA[128 * 20], sBh[128 * 20], sBl[128 * 20];

    const uint32_t* Xp = (const uint32_t*)g_xh;
    const uint32_t* Wh = (const uint32_t*)g_WiT_h;
    const uint32_t* Wl = (const uint32_t*)g_WiT_l;

    const int bn   = (blk & 31) * 128;
    const int bm   = (blk >> 5) * 128;
    const int lane = tid & 31, wp = tid >> 5;
    const int g    = lane >> 2, tq = lane & 3;
    const int wm   = (wp >> 2) * 64;
    const int wn   = (wp & 3) * 32;
    const int r0   = wp * 2 + (lane >> 4);
    const int kw   = lane & 15;

    float acc[4][4][4] = {};
    uint32_t pA[8], pBh[8], pBl[8];

    auto LOAD = [&](int kc) {
        int k0w = kc * 16;
#pragma unroll
        for (int i = 0; i < 8; i++) {
            int row = r0 + 16 * i;
            size_t ga = (size_t)(bm + row) * 512 + k0w + kw;
            size_t gb = (size_t)(bn + row) * 512 + k0w + kw;
            pA[i] = Xp[ga]; pBh[i] = Wh[gb]; pBl[i] = Wl[gb];
        }
    };
    auto STORE = [&]() {
#pragma unroll
        for (int i = 0; i < 8; i++) {
            int row = r0 + 16 * i;
            sA[row * 20 + kw]  = pA[i];
            sBh[row * 20 + kw] = pBh[i];
            sBl[row * 20 + kw] = pBl[i];
        }
    };

    LOAD(0); STORE(); __syncthreads();

    for (int kc = 0; kc < 32; kc++) {
        if (kc < 31) LOAD(kc + 1);
#pragma unroll
        for (int s = 0; s < 2; s++) {
            int kwb = s * 8;
            uint32_t bh[4][2], bl[4][2];
#pragma unroll
            for (int nf = 0; nf < 4; nf++) {
                int base = (wn + nf * 8 + g) * 20 + kwb + tq;
                bh[nf][0] = sBh[base]; bh[nf][1] = sBh[base + 4];
                bl[nf][0] = sBl[base]; bl[nf][1] = sBl[base + 4];
            }
#pragma unroll
            for (int mf = 0; mf < 4; mf++) {
                int rb = (wm + mf * 16 + g) * 20 + kwb + tq;
                uint32_t a0 = sA[rb], a1 = sA[rb + 160];
                uint32_t a2 = sA[rb + 4], a3 = sA[rb + 164];
#pragma unroll
                for (int nf = 0; nf < 4; nf++)
                    mma16816h(acc[mf][nf], a0, a1, a2, a3, bh[nf][0], bh[nf][1]);
#pragma unroll
                for (int nf = 0; nf < 4; nf++)
                    mma16816h(acc[mf][nf], a0, a1, a2, a3, bl[nf][0], bl[nf][1]);
            }
        }
        __syncthreads();
        if (kc < 31) { STORE(); __syncthreads(); }
    }

#pragma unroll
    for (int mf = 0; mf < 4; mf++) {
        int row0 = bm + wm + mf * 16 + g;
#pragma unroll
        for (int nf = 0; nf < 4; nf++) {
            int col = bn + wn + nf * 8 + tq * 2;
            float2 bb = *(const float2*)&bias[col];
            float2 v0, v1;
            v0.x = acc[mf][nf][0] + bb.x; v0.y = acc[mf][nf][1] + bb.y;
            v1.x = acc[mf][nf][2] + bb.x; v1.y = acc[mf][nf][3] + bb.y;
            *(float2*)&g_zx[(size_t)row0 * N4 + col]       = v0;
            *(float2*)&g_zx[(size_t)(row0 + 8) * N4 + col] = v1;
        }
    }
}

// ---------------------------------------------------------------------------
// Persistent recurrence (launch 3): 128 blocks x 256 thr.
// Dataflow sync; lane-0-elected spins with backoff to keep pollers off the
// hot counter lines. Flattened reduction; 2 syncthreads/step.
// ---------------------------------------------------------------------------
#define P_STRIDE    2112                   // 64*33 floats per ks slice
#define REC_SMEM    (131072 + 4 * P_STRIDE * 4)   // sB (128K) + P (33.8K)

__global__ __launch_bounds__(256, 1)
void lstm_rec_mma(const float* __restrict__ c0,
                  float* __restrict__ ys,
                  float* __restrict__ cT,
                  float* __restrict__ hT)
{
    extern __shared__ char dsm[];
    uint4* sB = (uint4*)dsm;                 // [hl(2)][nhalf(2)][kc64][lane32]
    float* P  = (float*)(dsm + 131072);      // [ks(4)][row(64)][col(33)]

    const int tid  = threadIdx.x, bid = blockIdx.x;
    const int lane = tid & 31, wp = tid >> 5;
    const int gq   = lane >> 2, tq = lane & 3;
    const int ks   = wp & 3;
    const int mp   = wp >> 2;
    const int jb   = bid * 8;
    const int myq  = bid >> 5;           // quarter this block produces

    // ---- load this block's Wh fragments into smem (once) ----
    {
        const uint4* GH = g_whfrag_hi + (size_t)bid * 4096;
        const uint4* GL = g_whfrag_lo + (size_t)bid * 4096;
#pragma unroll
        for (int i = 0; i < 16; i++) sB[tid + i * 256]        = GH[tid + i * 256];
#pragma unroll
        for (int i = 0; i < 16; i++) sB[4096 + tid + i * 256] = GL[tid + i * 256];
    }
    __syncthreads();

    // pointwise decode
    const int pb  = tid >> 2;
    const int jj  = (tid & 3) * 2;
    const int j0  = jb + jj;
    const int p_g   = j0 >> 1;
    const int kcw   = p_g >> 3, within = p_g & 7;
    const int ptq   = within & 3, pwhi = within >> 2;
    const int pm    = pb >> 4, r16 = pb & 15;
    const int pg    = r16 & 7, ptop = r16 >> 3;
    const uint32_t hoff = (uint32_t)((((pm * 64 + kcw) * 32) + pg * 4 + ptq) * 4
                                     + pwhi * 2 + ptop);

    for (int t = 0; t < T_; t++) {
        const uint4* AF = g_hfrag[t & 3];

        // ---- prefetch pointwise operands BEFORE the spin (t-only deps) ----
        const float* zx = g_zx + (size_t)t * BB * N4 + (size_t)pb * N4;
        const float* cp = (t == 0) ? c0 : cT;
        float2 xi = *(const float2*)&zx[j0];
        float2 xf = *(const float2*)&zx[HH + j0];
        float2 xg = *(const float2*)&zx[2 * HH + j0];
        float2 xo = *(const float2*)&zx[3 * HH + j0];
        float2 cv = *(const float2*)&cp[(size_t)pb * HH + j0];

        // ---- wait for this warp's input quarter (h cols produced at t-1) ----
        if (t > 0)
            spin_warp_acquire_ge(&g_readyq[t * 4 + ks], 32u);

        float accH[2][4][4], accL[2][4][4];
#pragma unroll
        for (int a = 0; a < 2; a++)
#pragma unroll
            for (int b = 0; b < 4; b++)
#pragma unroll
                for (int r = 0; r < 4; r++) { accH[a][b][r] = 0.f; accL[a][b][r] = 0.f; }

        // 4-slot pipeline for A (global); B read from smem per-iteration
        uint4 aF[4][2];
        const int kb = ks * 16;

        auto LOADA = [&](int i, int slot) {
            int off = (kb + i) * 32 + lane;
#pragma unroll
            for (int mm = 0; mm < 2; mm++)
                aF[slot][mm] = AF[(2 * mp + mm) * 2048 + off];
        };

        LOADA(0, 0); LOADA(1, 1); LOADA(2, 2);

#pragma unroll 4
        for (int i = 0; i < 16; i++) {
            int cur = i & 3;
            if (i + 3 < 16) LOADA(i + 3, (i + 3) & 3);

            int off = (kb + i) * 32 + lane;
            uint4 b0h = sB[off],        b1h = sB[2048 + off];
            uint4 b0l = sB[4096 + off], b1l = sB[6144 + off];
            uint4 a0 = aF[cur][0], a1 = aF[cur][1];

            // pass 1: h * W_hi  -> accH
            mma16816h(accH[0][0], a0.x, a0.y, a0.z, a0.w, b0h.x, b0h.y);
            mma16816h(accH[0][1], a0.x, a0.y, a0.z, a0.w, b0h.z, b0h.w);
            mma16816h(accH[0][2], a0.x, a0.y, a0.z, a0.w, b1h.x, b1h.y);
            mma16816h(accH[0][3], a0.x, a0.y, a0.z, a0.w, b1h.z, b1h.w);
            mma16816h(accH[1][0], a1.x, a1.y, a1.z, a1.w, b0h.x, b0h.y);
            mma16816h(accH[1][1], a1.x, a1.y, a1.z, a1.w, b0h.z, b0h.w);
            mma16816h(accH[1][2], a1.x, a1.y, a1.z, a1.w, b1h.x, b1h.y);
            mma16816h(accH[1][3], a1.x, a1.y, a1.z, a1.w, b1h.z, b1h.w);
            // pass 2: h * W_lo_scaled -> accL
            mma16816h(accL[0][0], a0.x, a0.y, a0.z, a0.w, b0l.x, b0l.y);
            mma16816h(accL[0][1], a0.x, a0.y, a0.z, a0.w, b0l.z, b0l.w);
            mma16816h(accL[0][2], a0.x, a0.y, a0.z, a0.w, b1l.x, b1l.y);
            mma16816h(accL[0][3], a0.x, a0.y, a0.z, a0.w, b1l.z, b1l.w);
            mma16816h(accL[1][0], a1.x, a1.y, a1.z, a1.w, b0l.x, b0l.y);
            mma16816h(accL[1][1], a1.x, a1.y, a1.z, a1.w, b0l.z, b0l.w);
            mma16816h(accL[1][2], a1.x, a1.y, a1.z, a1.w, b1l.x, b1l.y);
            mma16816h(accL[1][3], a1.x, a1.y, a1.z, a1.w, b1l.z, b1l.w);
        }

        // combine: z_part = accH + accL/2048; store ALL partials to P
        {
            float* Pk = P + ks * P_STRIDE;
#pragma unroll
            for (int mm = 0; mm < 2; mm++) {
                int row = mp * 32 + mm * 16 + gq;
#pragma unroll
                for (int nf = 0; nf < 4; nf++) {
                    int zb = (nf >> 1) * 16 + (nf & 1) * 8 + tq * 2;
                    float v0 = fmaf(accL[mm][nf][0], WLO_INV, accH[mm][nf][0]);
                    float v1 = fmaf(accL[mm][nf][1], WLO_INV, accH[mm][nf][1]);
                    float v2 = fmaf(accL[mm][nf][2], WLO_INV, accH[mm][nf][2]);
                    float v3 = fmaf(accL[mm][nf][3], WLO_INV, accH[mm][nf][3]);
                    Pk[row * 33 + zb]           = v0;
                    Pk[row * 33 + zb + 1]       = v1;
                    Pk[(row + 8) * 33 + zb]     = v2;
                    Pk[(row + 8) * 33 + zb + 1] = v3;
                }
            }
        }

        // A-reads for step t done -> signal; WAR wait for ring slot reuse
        if (tid == 255) atomicAdd(&g_read_done[t], 1u);
        if (t >= 3 && tid == 0) spin1_acquire_ge(&g_read_done[t - 3], 128u);
        __syncthreads();

        // ---- pointwise gates: sum 4 ks-partials directly (ascending ks) ----
        {
            float* ys_t = ys + (size_t)t * BB * HH;
            uint32_t* nh = (uint32_t*)g_hfrag[(t + 1) & 3];
            const float* Pr = P + pb * 33;

            float h2[2], c2[2];
#pragma unroll
            for (int e = 0; e < 2; e++) {
                int zc = jj + e;
                float zi = Pr[zc],      zf = Pr[8 + zc];
                float zg = Pr[16 + zc], zo = Pr[24 + zc];
#pragma unroll
                for (int s = 1; s < 4; s++) {
                    const float* Ps = Pr + s * P_STRIDE;
                    zi += Ps[zc];      zf += Ps[8 + zc];
                    zg += Ps[16 + zc]; zo += Ps[24 + zc];
                }
                zi += (e ? xi.y : xi.x);
                zf += (e ? xf.y : xf.x);
                zg += (e ? xg.y : xg.x);
                zo += (e ? xo.y : xo.x);

                float ig = fast_sigmoid(zi);
                float fg = fast_sigmoid(zf);
                float gg = fast_tanh(zg);
                float og = fast_sigmoid(zo);

                float cc = fg * (e ? cv.y : cv.x) + ig * gg;
                c2[e] = cc;
                h2[e] = og * fast_tanh(cc);
            }

            *(float2*)&cT[(size_t)pb * HH + j0]   = *(float2*)c2;
            *(float2*)&ys_t[(size_t)pb * HH + j0] = *(float2*)h2;
            if (t == T_ - 1) *(float2*)&hT[(size_t)pb * HH + j0] = *(float2*)h2;

            __half2 hv = __floats2half2_rn(h2[0], h2[1]);
            nh[hoff] = *(uint32_t*)&hv;
        }

        // ---- release: h cols for step t+1 are written ----
        __syncthreads();
        if (tid == 0 && t + 1 < T_) {
            __threadfence();
            atomicAdd(&g_readyq[(t + 1) * 4 + myq], 1u);
        }
    }
}

// ---------------------------------------------------------------------------
extern "C" void kernel_launch(void* const* d_in, const int* in_sizes, int n_in,
                              void* d_out, int out_size)
{
    const float* x  = (const float*)d_in[0];   // [T,B,D]
    const float* c0 = (const float*)d_in[1];   // [B,H]
    const float* h0 = (const float*)d_in[2];   // [B,H]
    const float* Wi = (const float*)d_in[3];   // [D,4H]
    const float* Wh = (const float*)d_in[4];   // [H,4H]
    const float* b  = (const float*)d_in[5];   // [4H]

    float* out = (float*)d_out;
    float* ys = out;                                  // [T,B,H]
    float* cT = out + (size_t)T_ * BB * HH;           // [B,H]
    float* hT = cT + (size_t)BB * HH;                 // [B,H]

    static unsigned int* d_rq = nullptr;
    static unsigned int* d_rd = nullptr;
    static int rec_smem_set = 0;
    if (!rec_smem_set) {
        cudaFuncSetAttribute(lstm_rec_mma,
                             cudaFuncAttributeMaxDynamicSharedMemorySize, REC_SMEM);
        cudaGetSymbolAddress((void**)&d_rq, g_readyq);
        cudaGetSymbolAddress((void**)&d_rd, g_read_done);
        rec_smem_set = 1;
    }

    // zero dataflow counters (graph-legal async memset nodes)
    cudaMemsetAsync(d_rq, 0, sizeof(unsigned int) * (T_ + 1) * 4);
    cudaMemsetAsync(d_rd, 0, sizeof(unsigned int) * T_);

    prep_fused<<<16512, 256>>>(x, Wi, Wh, h0);               // launch 1
    gemm_wx_pack<<<10240, 256>>>(b);                         // launch 2
    lstm_rec_mma<<<RGRID, 256, REC_SMEM>>>(c0, ys, cT, hT);  // launch 3
}